// round 1
// baseline (speedup 1.0000x reference)
#include <cuda_runtime.h>
#include <math.h>

#define B_    4
#define N_    8000
#define FIN   256
#define DD    128
#define DFF   128
#define NBINS 16
#define BINSZ 500
#define KNN   8
#define E_TOT (B_*N_*KNN)     /* 256000 */
#define ROTC  100             /* MAX_NUM_BINS/2, row stride of rot */

// ---------------- scratch (static device globals; no allocation) -------------
__device__ float g_pe[B_*N_*DD];      // encoded points
__device__ int   g_bin[B_*N_];        // LSH bin per point
__device__ int   g_perm[B_*N_];       // stable argsort by bin == bins_split
__device__ int   g_dst[E_TOT];        // per (b,src,slot) global dst, dst-sorted
__device__ float g_val[E_TOT];        // matching kernel values

// ---------------- kernel 1: encoder FFN + LSH bin index ----------------------
__global__ void enc_kernel(const float* __restrict__ inputs,
                           const float* __restrict__ w1, const float* __restrict__ b1,
                           const float* __restrict__ w2, const float* __restrict__ b2,
                           const float* __restrict__ rot) {
    __shared__ float xs[FIN];
    __shared__ float hs[DFF];
    __shared__ float ps[DD];
    __shared__ float ms[NBINS/2];
    int n = blockIdx.x;            // 0..31999 (b*N + point)
    int tid = threadIdx.x;         // 128
    const float* x = inputs + (size_t)n * FIN;
    for (int i = tid; i < FIN; i += 128) xs[i] = x[i];
    __syncthreads();
    float a = 0.f;
    #pragma unroll 8
    for (int i = 0; i < FIN; ++i) a += xs[i] * w1[i*DFF + tid];
    a += b1[tid];
    hs[tid] = a > 0.f ? a : expm1f(a);
    __syncthreads();
    float o = 0.f;
    #pragma unroll 8
    for (int k = 0; k < DFF; ++k) o += hs[k] * w2[k*DD + tid];
    o += b2[tid];
    ps[tid] = o;
    g_pe[(size_t)n*DD + tid] = o;
    __syncthreads();
    if (tid < NBINS/2) {
        float m = 0.f;
        for (int d = 0; d < DD; ++d) m += ps[d] * rot[d*ROTC + tid];
        ms[tid] = m;
    }
    __syncthreads();
    if (tid == 0) {
        float best = ms[0]; int bi = 0;
        for (int j = 1; j < NBINS; ++j) {
            float v = (j < NBINS/2) ? ms[j] : -ms[j - NBINS/2];
            if (v > best) { best = v; bi = j; }   // strict > keeps first max
        }
        g_bin[n] = bi;
    }
}

// ---------------- kernel 2: stable counting sort per batch -------------------
__global__ void sort_kernel() {
    int b = blockIdx.x;
    __shared__ int bins[N_];
    __shared__ int cnt[NBINS];
    __shared__ int offs[NBINS];
    __shared__ int wtot[8];
    int tid = threadIdx.x;         // 256
    int wid = tid >> 5, lane = tid & 31;
    for (int i = tid; i < N_; i += 256) bins[i] = g_bin[b*N_ + i];
    if (tid < NBINS) cnt[tid] = 0;
    __syncthreads();
    for (int i = tid; i < N_; i += 256) atomicAdd(&cnt[bins[i]], 1);
    __syncthreads();
    if (tid == 0) { int s = 0; for (int k = 0; k < NBINS; ++k) { offs[k] = s; s += cnt[k]; } }
    __syncthreads();
    for (int bin = 0; bin < NBINS; ++bin) {
        int base = offs[bin];
        for (int c0 = 0; c0 < N_; c0 += 256) {
            int i = c0 + tid;
            int flag = (i < N_ && bins[i] == bin) ? 1 : 0;
            unsigned m = __ballot_sync(0xffffffffu, flag);
            int wpre = __popc(m & ((1u << lane) - 1u));
            if (lane == 0) wtot[wid] = __popc(m);
            __syncthreads();
            int woff = 0;
            for (int w = 0; w < wid; ++w) woff += wtot[w];
            int tot = 0;
            for (int w = 0; w < 8; ++w) tot += wtot[w];
            if (flag) g_perm[b*N_ + base + woff + wpre] = i;
            base += tot;
            __syncthreads();
        }
    }
}

// ---------------- kernel 3: per-(batch,bin) pairwise top-8 -------------------
// Block = one (b,bin). 256 threads; 4 threads per row; row point cached in regs.
__device__ __forceinline__ bool better(float av, int ai, float bv, int bi) {
    return (av > bv) || (av == bv && ai < bi);
}

__global__ void topk_kernel() {
    int bb = blockIdx.x;
    int b = bb / NBINS, bin = bb % NBINS;
    extern __shared__ float4 colbuf[];                // [128 cols][32 float4]
    const int* perm = g_perm + b*N_ + bin*BINSZ;
    const float* pe = g_pe + (size_t)b*N_*DD;
    int tid = threadIdx.x;
    int rl = tid >> 2, l4 = tid & 3;                  // 64 rows, 4 lanes each

    for (int rc = 0; rc < BINSZ; rc += 64) {
        int row = rc + rl;
        bool rvalid = row < BINSZ;
        int rowc = rvalid ? row : (BINSZ - 1);
        float4 rp[8];
        {
            const float4* prow = (const float4*)(pe + (size_t)perm[rowc]*DD) + l4*8;
            #pragma unroll
            for (int kk = 0; kk < 8; ++kk) rp[kk] = prow[kk];
        }
        float tv[KNN]; int ti[KNN];
        #pragma unroll
        for (int s = 0; s < KNN; ++s) { tv[s] = -1.0f; ti[s] = 1 << 30; }

        for (int cc = 0; cc < BINSZ; cc += 128) {
            int csize = min(128, BINSZ - cc);
            __syncthreads();
            for (int t = tid; t < csize*32; t += 256) {
                int c = t >> 5, k = t & 31;
                colbuf[c*32 + k] = ((const float4*)(pe + (size_t)perm[cc + c]*DD))[k];
            }
            __syncthreads();
            for (int c = 0; c < csize; ++c) {
                float part = 0.f;
                #pragma unroll
                for (int kk = 0; kk < 8; ++kk) {
                    int ke = (kk + 2*l4) & 7;                     // bank stagger
                    float4 cp = colbuf[c*32 + l4*8 + ke];
                    float4 rv = rp[ke];
                    float dx = rv.x - cp.x, dy = rv.y - cp.y;
                    float dz = rv.z - cp.z, dw = rv.w - cp.w;
                    part += dx*dx + dy*dy + dz*dz + dw*dw;
                }
                part += __shfl_down_sync(0xffffffffu, part, 2, 4);
                part += __shfl_down_sync(0xffffffffu, part, 1, 4);
                if (l4 == 0) {
                    float dm = expf(-0.1f * sqrtf(fmaxf(part, 1e-6f)));
                    int gi = cc + c;                               // in-bin index
                    if (better(dm, gi, tv[KNN-1], ti[KNN-1])) {
                        tv[KNN-1] = dm; ti[KNN-1] = gi;
                        #pragma unroll
                        for (int s = KNN-1; s > 0; --s) {
                            if (better(tv[s], ti[s], tv[s-1], ti[s-1])) {
                                float fv = tv[s]; tv[s] = tv[s-1]; tv[s-1] = fv;
                                int   fi = ti[s]; ti[s] = ti[s-1]; ti[s-1] = fi;
                            }
                        }
                    }
                }
            }
        }
        if (rvalid && l4 == 0) {
            int src = perm[row];
            int dsts[KNN]; float vals[KNN];
            #pragma unroll
            for (int s = 0; s < KNN; ++s) { dsts[s] = perm[ti[s]]; vals[s] = tv[s]; }
            // sort the 8 neighbors by dst ascending (matches lexsort)
            #pragma unroll
            for (int i = 1; i < KNN; ++i) {
                int dk = dsts[i]; float vk = vals[i]; int j = i - 1;
                while (j >= 0 && dsts[j] > dk) {
                    dsts[j+1] = dsts[j]; vals[j+1] = vals[j]; --j;
                }
                dsts[j+1] = dk; vals[j+1] = vk;
            }
            size_t base = ((size_t)b*N_ + src) * KNN;
            #pragma unroll
            for (int s = 0; s < KNN; ++s) { g_dst[base+s] = dsts[s]; g_val[base+s] = vals[s]; }
        }
    }
}

// ---------------- kernel 4: edge FFN (gather + GEMM + epilogue) --------------
// Block: 64 edge rows x 128 hidden cols. smem: e rows [64][520], w1 chunk [64][128].
#define ESTR 520
__global__ void edge_kernel(const float* __restrict__ inputs,
                            const float* __restrict__ w1, const float* __restrict__ b1,
                            const float* __restrict__ w2, const float* __restrict__ b2v,
                            float* __restrict__ out, int out_size) {
    extern __shared__ float sm[];
    float* esm = sm;                        // 64*520 floats
    float* wsm = sm + 64*ESTR;              // 64*128 floats
    __shared__ float b1s[DFF], w2s[DFF];
    int tid = threadIdx.x;                  // 256
    int e0 = blockIdx.x * 64;
    if (tid < DFF) { b1s[tid] = b1[tid]; w2s[tid] = w2[tid]; }
    int wid = tid >> 5, lane = tid & 31;
    for (int r = wid; r < 64; r += 8) {
        int eid = e0 + r;
        int b   = eid / (N_ * KNN);
        int src = (eid % (N_ * KNN)) / KNN;
        int dst = g_dst[eid];
        const float4* x1 = (const float4*)(inputs + ((size_t)b*N_ + src)*FIN);
        const float4* x2 = (const float4*)(inputs + ((size_t)b*N_ + dst)*FIN);
        float4* er = (float4*)(esm + r*ESTR);
        for (int k = lane; k < 64; k += 32) { er[k] = x1[k]; er[64 + k] = x2[k]; }
        if (lane == 0) esm[r*ESTR + 512] = g_val[eid];
    }
    float acc[8][4];
    #pragma unroll
    for (int rr = 0; rr < 8; ++rr) { acc[rr][0]=acc[rr][1]=acc[rr][2]=acc[rr][3]=0.f; }
    int ty = tid >> 5, tx = tid & 31;
    for (int kc = 0; kc < 2*FIN + 1; kc += 64) {
        int ks = min(64, 2*FIN + 1 - kc);
        __syncthreads();
        for (int t = tid; t < ks*32; t += 256) {
            int k = t >> 5, j4 = t & 31;
            ((float4*)wsm)[k*32 + j4] = ((const float4*)(w1 + (size_t)(kc + k)*DFF))[j4];
        }
        __syncthreads();
        for (int k = 0; k < ks; ++k) {
            float4 wv = ((float4*)wsm)[k*32 + tx];
            #pragma unroll
            for (int rr = 0; rr < 8; ++rr) {
                float ev = esm[(ty*8 + rr)*ESTR + kc + k];
                acc[rr][0] += ev * wv.x; acc[rr][1] += ev * wv.y;
                acc[rr][2] += ev * wv.z; acc[rr][3] += ev * wv.w;
            }
        }
    }
    float b2s = b2v[0];
    #pragma unroll
    for (int rr = 0; rr < 8; ++rr) {
        float p = 0.f;
        #pragma unroll
        for (int c = 0; c < 4; ++c) {
            float h = acc[rr][c] + b1s[tx*4 + c];
            h = h > 0.f ? h : expm1f(h);
            p += h * w2s[tx*4 + c];
        }
        #pragma unroll
        for (int off = 16; off; off >>= 1) p += __shfl_down_sync(0xffffffffu, p, off);
        if (tx == 0) {
            int idx = 3*E_TOT + e0 + ty*8 + rr;
            if (idx < out_size) out[idx] = 1.f / (1.f + expf(-(p + b2s)));
        }
    }
}

// ---------------- kernel 5: assemble indices + bins_split --------------------
__global__ void assemble_kernel(float* __restrict__ out, int out_size) {
    int i = blockIdx.x * blockDim.x + threadIdx.x;
    if (i < E_TOT) {
        int b   = i / (N_ * KNN);
        int src = (i % (N_ * KNN)) / KNN;
        if (i*3 + 2 < out_size) {
            out[i*3 + 0] = (float)b;
            out[i*3 + 1] = (float)src;
            out[i*3 + 2] = (float)g_dst[i];
        }
    }
    if (i < B_*N_) {
        int idx = 4*E_TOT + i;
        if (idx < out_size) out[idx] = (float)g_perm[i];
    }
}

// -----------------------------------------------------------------------------
extern "C" void kernel_launch(void* const* d_in, const int* in_sizes, int n_in,
                              void* d_out, int out_size) {
    const float* inputs  = (const float*)d_in[0];
    const float* enc_w1  = (const float*)d_in[1];
    const float* enc_b1  = (const float*)d_in[2];
    const float* enc_w2  = (const float*)d_in[3];
    const float* enc_b2  = (const float*)d_in[4];
    const float* edge_w1 = (const float*)d_in[5];
    const float* edge_b1 = (const float*)d_in[6];
    const float* edge_w2 = (const float*)d_in[7];
    const float* edge_b2 = (const float*)d_in[8];
    const float* rot     = (const float*)d_in[9];
    float* out = (float*)d_out;

    enc_kernel<<<B_*N_, 128>>>(inputs, enc_w1, enc_b1, enc_w2, enc_b2, rot);
    sort_kernel<<<B_, 256>>>();

    size_t tk_smem = 128 * 32 * sizeof(float4);       // 64 KB
    cudaFuncSetAttribute(topk_kernel, cudaFuncAttributeMaxDynamicSharedMemorySize,
                         (int)tk_smem);
    topk_kernel<<<B_*NBINS, 256, tk_smem>>>();

    size_t eg_smem = (size_t)(64*ESTR + 64*DFF) * sizeof(float);   // ~166 KB
    cudaFuncSetAttribute(edge_kernel, cudaFuncAttributeMaxDynamicSharedMemorySize,
                         (int)eg_smem);
    edge_kernel<<<E_TOT/64, 256, eg_smem>>>(inputs, edge_w1, edge_b1, edge_w2, edge_b2,
                                            out, out_size);

    assemble_kernel<<<(E_TOT + 255)/256, 256>>>(out, out_size);
}

// round 2
// speedup vs baseline: 1.7513x; 1.7513x over previous
#include <cuda_runtime.h>
#include <math.h>

#define B_    4
#define N_    8000
#define FIN   256
#define DD    128
#define DFF   128
#define NBINS 16
#define BINSZ 500
#define KNN   8
#define E_TOT (B_*N_*KNN)     /* 256000 */
#define ROTC  100             /* MAX_NUM_BINS/2, row stride of rot */

// ---------------- scratch (static device globals; no allocation) -------------
__device__ float g_pe[B_*N_*DD];      // encoded points
__device__ float g_norm[B_*N_];       // squared norms of encoded points
__device__ int   g_bin[B_*N_];        // LSH bin per point
__device__ int   g_perm[B_*N_];       // stable argsort by bin == bins_split
__device__ int   g_dst[E_TOT];        // per (b,src,slot) global dst, dst-sorted
__device__ float g_val[E_TOT];        // matching kernel values

// ---------------- packed f32x2 helpers ---------------------------------------
#define FMA2(d, a, b) asm("fma.rn.f32x2 %0, %1, %2, %0;" : "+l"(d) : "l"(a), "l"(b))

__device__ __forceinline__ unsigned long long dup2(float v) {
    unsigned iv = __float_as_uint(v);
    unsigned long long r;
    asm("mov.b64 %0, {%1, %1};" : "=l"(r) : "r"(iv), "r"(iv));
    return r;
}
__device__ __forceinline__ float f2lo(unsigned long long u) {
    return __uint_as_float((unsigned)u);
}
__device__ __forceinline__ float f2hi(unsigned long long u) {
    return __uint_as_float((unsigned)(u >> 32));
}

// ---------------- kernel 1: tiled encoder FFN + norms + LSH bin --------------
// Block = 128 points, 512 threads (16 warps x 8 points each), f32x2 GEMM.
#define ENC_PTS 128
__global__ __launch_bounds__(512) void enc_kernel(
        const float* __restrict__ inputs,
        const float* __restrict__ w1, const float* __restrict__ b1,
        const float* __restrict__ w2, const float* __restrict__ b2,
        const float* __restrict__ rot) {
    extern __shared__ float sm[];
    float* r0 = sm;                 // 16384 floats: xs+ws (phase1), w2 (phase2)
    float* xs = sm;                 // [128][64]
    float* ws = sm + 8192;          // [64][128]
    float* hs = sm + 16384;         // [128][128] hidden, later reused as output
    __shared__ float b1s[DFF], b2s[DD];
    __shared__ float rots[DD * 8];
    __shared__ float ms[ENC_PTS][8];
    int tid = threadIdx.x;
    int wid = tid >> 5, tx = tid & 31;
    int n0 = blockIdx.x * ENC_PTS;

    if (tid < DFF) b1s[tid] = b1[tid];
    else if (tid < DFF + DD) b2s[tid - DFF] = b2[tid - DFF];
    for (int t = tid; t < DD * 8; t += 512) {
        int d = t >> 3, j = t & 7;
        rots[t] = rot[d * ROTC + j];
    }

    // ---- phase 1: H = elu(X @ W1 + b1) ----
    unsigned long long acc[8][2];
    #pragma unroll
    for (int rr = 0; rr < 8; ++rr) { acc[rr][0] = 0ull; acc[rr][1] = 0ull; }

    for (int kc = 0; kc < FIN; kc += 64) {
        __syncthreads();
        for (int t = tid; t < 2048; t += 512) {            // X tile [128][64]
            int p = t >> 4, k4 = t & 15;
            ((float4*)xs)[p * 16 + k4] =
                ((const float4*)(inputs + (size_t)(n0 + p) * FIN + kc))[k4];
        }
        for (int t = tid; t < 2048; t += 512) {            // W1 chunk [64][128]
            int k = t >> 5, c4 = t & 31;
            ((float4*)ws)[k * 32 + c4] =
                ((const float4*)(w1 + (size_t)(kc + k) * DFF))[c4];
        }
        __syncthreads();
        for (int k4 = 0; k4 < 64; k4 += 4) {
            float4 e4[8];
            #pragma unroll
            for (int rr = 0; rr < 8; ++rr)
                e4[rr] = *(const float4*)&xs[(wid * 8 + rr) * 64 + k4];
            #pragma unroll
            for (int j = 0; j < 4; ++j) {
                ulonglong2 wp = *(const ulonglong2*)&ws[(k4 + j) * DFF + tx * 4];
                #pragma unroll
                for (int rr = 0; rr < 8; ++rr) {
                    float ev = (j == 0) ? e4[rr].x : (j == 1) ? e4[rr].y
                             : (j == 2) ? e4[rr].z : e4[rr].w;
                    unsigned long long ed = dup2(ev);
                    FMA2(acc[rr][0], ed, wp.x);
                    FMA2(acc[rr][1], ed, wp.y);
                }
            }
        }
    }
    // elu + bias -> hs
    #pragma unroll
    for (int rr = 0; rr < 8; ++rr) {
        int p = wid * 8 + rr;
        float h0 = f2lo(acc[rr][0]) + b1s[tx * 4 + 0];
        float h1 = f2hi(acc[rr][0]) + b1s[tx * 4 + 1];
        float h2 = f2lo(acc[rr][1]) + b1s[tx * 4 + 2];
        float h3 = f2hi(acc[rr][1]) + b1s[tx * 4 + 3];
        h0 = h0 > 0.f ? h0 : expm1f(h0);
        h1 = h1 > 0.f ? h1 : expm1f(h1);
        h2 = h2 > 0.f ? h2 : expm1f(h2);
        h3 = h3 > 0.f ? h3 : expm1f(h3);
        float4 hv = make_float4(h0, h1, h2, h3);
        *(float4*)&hs[p * DFF + tx * 4] = hv;
    }
    __syncthreads();

    // ---- phase 2: O = H @ W2 + b2 ----
    for (int t = tid; t < 4096; t += 512)                  // full W2 [128][128]
        ((float4*)r0)[t] = ((const float4*)w2)[t];
    __syncthreads();

    #pragma unroll
    for (int rr = 0; rr < 8; ++rr) { acc[rr][0] = 0ull; acc[rr][1] = 0ull; }
    for (int k4 = 0; k4 < DFF; k4 += 4) {
        float4 e4[8];
        #pragma unroll
        for (int rr = 0; rr < 8; ++rr)
            e4[rr] = *(const float4*)&hs[(wid * 8 + rr) * DFF + k4];
        #pragma unroll
        for (int j = 0; j < 4; ++j) {
            ulonglong2 wp = *(const ulonglong2*)&r0[(k4 + j) * DD + tx * 4];
            #pragma unroll
            for (int rr = 0; rr < 8; ++rr) {
                float ev = (j == 0) ? e4[rr].x : (j == 1) ? e4[rr].y
                         : (j == 2) ? e4[rr].z : e4[rr].w;
                unsigned long long ed = dup2(ev);
                FMA2(acc[rr][0], ed, wp.x);
                FMA2(acc[rr][1], ed, wp.y);
            }
        }
    }
    __syncthreads();   // all hs reads done before overwrite below
    #pragma unroll
    for (int rr = 0; rr < 8; ++rr) {
        int p = wid * 8 + rr;
        int n = n0 + p;
        float o0 = f2lo(acc[rr][0]) + b2s[tx * 4 + 0];
        float o1 = f2hi(acc[rr][0]) + b2s[tx * 4 + 1];
        float o2 = f2lo(acc[rr][1]) + b2s[tx * 4 + 2];
        float o3 = f2hi(acc[rr][1]) + b2s[tx * 4 + 3];
        float4 ov = make_float4(o0, o1, o2, o3);
        *(float4*)&hs[p * DD + tx * 4] = ov;               // os overlays hs (own rows)
        *(float4*)&g_pe[(size_t)n * DD + tx * 4] = ov;
        float pn = o0 * o0 + o1 * o1 + o2 * o2 + o3 * o3;
        #pragma unroll
        for (int off = 16; off; off >>= 1)
            pn += __shfl_xor_sync(0xffffffffu, pn, off);
        if (tx == 0) g_norm[n] = pn;
    }
    __syncthreads();

    // ---- phase 3: rot projection + argmax bin ----
    for (int t = tid; t < ENC_PTS * 8; t += 512) {
        int p = t >> 3, j = t & 7;
        float m = 0.f;
        #pragma unroll 8
        for (int d = 0; d < DD; ++d) m += hs[p * DD + d] * rots[d * 8 + j];
        ms[p][j] = m;
    }
    __syncthreads();
    if (tid < ENC_PTS) {
        float best = ms[tid][0]; int bi = 0;
        #pragma unroll
        for (int j = 1; j < NBINS; ++j) {
            float v = (j < 8) ? ms[tid][j] : -ms[tid][j - 8];
            if (v > best) { best = v; bi = j; }
        }
        g_bin[n0 + tid] = bi;
    }
}

// ---------------- kernel 2: stable counting sort per batch -------------------
__global__ void sort_kernel() {
    int b = blockIdx.x;
    __shared__ int bins[N_];
    __shared__ int cnt[NBINS];
    __shared__ int offs[NBINS];
    __shared__ int wtot[8];
    int tid = threadIdx.x;         // 256
    int wid = tid >> 5, lane = tid & 31;
    for (int i = tid; i < N_; i += 256) bins[i] = g_bin[b*N_ + i];
    if (tid < NBINS) cnt[tid] = 0;
    __syncthreads();
    for (int i = tid; i < N_; i += 256) atomicAdd(&cnt[bins[i]], 1);
    __syncthreads();
    if (tid == 0) { int s = 0; for (int k = 0; k < NBINS; ++k) { offs[k] = s; s += cnt[k]; } }
    __syncthreads();
    for (int bin = 0; bin < NBINS; ++bin) {
        int base = offs[bin];
        for (int c0 = 0; c0 < N_; c0 += 256) {
            int i = c0 + tid;
            int flag = (i < N_ && bins[i] == bin) ? 1 : 0;
            unsigned m = __ballot_sync(0xffffffffu, flag);
            int wpre = __popc(m & ((1u << lane) - 1u));
            if (lane == 0) wtot[wid] = __popc(m);
            __syncthreads();
            int woff = 0;
            for (int w = 0; w < wid; ++w) woff += wtot[w];
            int tot = 0;
            for (int w = 0; w < 8; ++w) tot += wtot[w];
            if (flag) g_perm[b*N_ + base + woff + wpre] = i;
            base += tot;
            __syncthreads();
        }
    }
}

// ---------------- kernel 3: per-(batch,bin,rowgroup) pairwise top-8 ----------
// 256 blocks = 64 (b,bin) x 4 row groups of 125 rows. dot-product + norms form.
__device__ __forceinline__ bool better(float av, int ai, float bv, int bi) {
    return (av > bv) || (av == bv && ai < bi);
}

__global__ void topk_kernel() {
    int bb = blockIdx.x;
    int rg = bb & 3;
    int bbin = bb >> 2;
    int b = bbin / NBINS, bin = bbin % NBINS;
    extern __shared__ float smx[];
    float4* colbuf = (float4*)smx;                 // [128 cols][32 float4]
    float* cnorm = smx + 128 * 32 * 4;             // [128]
    const int* perm = g_perm + b*N_ + bin*BINSZ;
    const float* pe = g_pe + (size_t)b*N_*DD;
    int tid = threadIdx.x;
    int rl = tid >> 2, l4 = tid & 3;               // 64 rows/chunk, 4 lanes/row
    int rbase = rg * 125;

    for (int rc = 0; rc < 125; rc += 64) {
        int rloc = rc + rl;
        bool rvalid = rloc < 125;
        int row = rbase + (rvalid ? rloc : 0);
        int rsrc = perm[row];
        ulonglong2 rp[8];
        {
            const ulonglong2* prow = (const ulonglong2*)(pe + (size_t)rsrc*DD) + l4*8;
            #pragma unroll
            for (int kk = 0; kk < 8; ++kk) rp[kk] = prow[kk];
        }
        float rn = g_norm[b*N_ + rsrc];
        float tv[KNN]; int ti[KNN];
        #pragma unroll
        for (int s = 0; s < KNN; ++s) { tv[s] = -1.0f; ti[s] = 1 << 30; }

        for (int cc = 0; cc < BINSZ; cc += 128) {
            int csize = min(128, BINSZ - cc);
            __syncthreads();
            for (int t = tid; t < csize*32; t += 256) {
                int c = t >> 5, k = t & 31;
                colbuf[c*32 + k] = ((const float4*)(pe + (size_t)perm[cc + c]*DD))[k];
            }
            for (int t = tid; t < csize; t += 256)
                cnorm[t] = g_norm[b*N_ + perm[cc + t]];
            __syncthreads();
            for (int c = 0; c < csize; ++c) {
                unsigned long long a0 = 0ull, a1 = 0ull;
                #pragma unroll
                for (int kk = 0; kk < 8; ++kk) {
                    int ke = (kk + 2*l4) & 7;                     // bank stagger
                    ulonglong2 cp = *(const ulonglong2*)&colbuf[c*32 + l4*8 + ke];
                    FMA2(a0, rp[ke].x, cp.x);
                    FMA2(a1, rp[ke].y, cp.y);
                }
                float part = f2lo(a0) + f2hi(a0) + f2lo(a1) + f2hi(a1);
                part += __shfl_down_sync(0xffffffffu, part, 2, 4);
                part += __shfl_down_sync(0xffffffffu, part, 1, 4);
                if (l4 == 0) {
                    float d2 = (rn - 2.0f * part) + cnorm[c];
                    float dm = expf(-0.1f * sqrtf(fmaxf(d2, 1e-6f)));
                    int gi = cc + c;
                    if (better(dm, gi, tv[KNN-1], ti[KNN-1])) {
                        tv[KNN-1] = dm; ti[KNN-1] = gi;
                        #pragma unroll
                        for (int s = KNN-1; s > 0; --s) {
                            if (better(tv[s], ti[s], tv[s-1], ti[s-1])) {
                                float fv = tv[s]; tv[s] = tv[s-1]; tv[s-1] = fv;
                                int   fi = ti[s]; ti[s] = ti[s-1]; ti[s-1] = fi;
                            }
                        }
                    }
                }
            }
        }
        if (rvalid && l4 == 0) {
            int src = rsrc;
            int dsts[KNN]; float vals[KNN];
            #pragma unroll
            for (int s = 0; s < KNN; ++s) { dsts[s] = perm[ti[s]]; vals[s] = tv[s]; }
            #pragma unroll
            for (int i = 1; i < KNN; ++i) {
                int dk = dsts[i]; float vk = vals[i]; int j = i - 1;
                while (j >= 0 && dsts[j] > dk) {
                    dsts[j+1] = dsts[j]; vals[j+1] = vals[j]; --j;
                }
                dsts[j+1] = dk; vals[j+1] = vk;
            }
            size_t base = ((size_t)b*N_ + src) * KNN;
            #pragma unroll
            for (int s = 0; s < KNN; ++s) { g_dst[base+s] = dsts[s]; g_val[base+s] = vals[s]; }
        }
    }
}

// ---------------- kernel 4: edge FFN (gather + f32x2 GEMM + epilogue) --------
#define ESTR 520
__global__ __launch_bounds__(256) void edge_kernel(
        const float* __restrict__ inputs,
        const float* __restrict__ w1, const float* __restrict__ b1,
        const float* __restrict__ w2, const float* __restrict__ b2v,
        float* __restrict__ out, int out_size) {
    extern __shared__ float sm[];
    float* esm = sm;                        // 64*520 floats
    float* wsm = sm + 64*ESTR;              // 64*128 floats
    __shared__ float b1s[DFF], w2s[DFF];
    int tid = threadIdx.x;                  // 256
    int e0 = blockIdx.x * 64;
    if (tid < DFF) { b1s[tid] = b1[tid]; w2s[tid] = w2[tid]; }
    int wid = tid >> 5, lane = tid & 31;
    for (int r = wid; r < 64; r += 8) {
        int eid = e0 + r;
        int b   = eid / (N_ * KNN);
        int src = (eid % (N_ * KNN)) / KNN;
        int dst = g_dst[eid];
        const float4* x1 = (const float4*)(inputs + ((size_t)b*N_ + src)*FIN);
        const float4* x2 = (const float4*)(inputs + ((size_t)b*N_ + dst)*FIN);
        float4* er = (float4*)(esm + r*ESTR);
        for (int k = lane; k < 64; k += 32) { er[k] = x1[k]; er[64 + k] = x2[k]; }
        if (lane == 0) esm[r*ESTR + 512] = g_val[eid];
    }
    unsigned long long acc[8][2];
    #pragma unroll
    for (int rr = 0; rr < 8; ++rr) { acc[rr][0] = 0ull; acc[rr][1] = 0ull; }
    int ty = tid >> 5, tx = tid & 31;
    for (int kc = 0; kc < 512; kc += 64) {
        __syncthreads();
        for (int t = tid; t < 64*32; t += 256) {
            int k = t >> 5, j4 = t & 31;
            ((float4*)wsm)[k*32 + j4] = ((const float4*)(w1 + (size_t)(kc + k)*DFF))[j4];
        }
        __syncthreads();
        for (int k4 = 0; k4 < 64; k4 += 4) {
            float4 e4[8];
            #pragma unroll
            for (int rr = 0; rr < 8; ++rr)
                e4[rr] = *(const float4*)&esm[(ty*8 + rr)*ESTR + kc + k4];
            #pragma unroll
            for (int j = 0; j < 4; ++j) {
                ulonglong2 wp = *(const ulonglong2*)&wsm[(k4 + j)*DFF + tx*4];
                #pragma unroll
                for (int rr = 0; rr < 8; ++rr) {
                    float ev = (j == 0) ? e4[rr].x : (j == 1) ? e4[rr].y
                             : (j == 2) ? e4[rr].z : e4[rr].w;
                    unsigned long long ed = dup2(ev);
                    FMA2(acc[rr][0], ed, wp.x);
                    FMA2(acc[rr][1], ed, wp.y);
                }
            }
        }
    }
    // last k = 512 (the kernel value column)
    {
        ulonglong2 wl = *(const ulonglong2*)&w1[(size_t)512*DFF + tx*4];
        #pragma unroll
        for (int rr = 0; rr < 8; ++rr) {
            unsigned long long ed = dup2(esm[(ty*8 + rr)*ESTR + 512]);
            FMA2(acc[rr][0], ed, wl.x);
            FMA2(acc[rr][1], ed, wl.y);
        }
    }
    float b2s = b2v[0];
    #pragma unroll
    for (int rr = 0; rr < 8; ++rr) {
        float h0 = f2lo(acc[rr][0]) + b1s[tx*4 + 0];
        float h1 = f2hi(acc[rr][0]) + b1s[tx*4 + 1];
        float h2 = f2lo(acc[rr][1]) + b1s[tx*4 + 2];
        float h3 = f2hi(acc[rr][1]) + b1s[tx*4 + 3];
        h0 = h0 > 0.f ? h0 : expm1f(h0);
        h1 = h1 > 0.f ? h1 : expm1f(h1);
        h2 = h2 > 0.f ? h2 : expm1f(h2);
        h3 = h3 > 0.f ? h3 : expm1f(h3);
        float p = h0 * w2s[tx*4+0] + h1 * w2s[tx*4+1]
                + h2 * w2s[tx*4+2] + h3 * w2s[tx*4+3];
        #pragma unroll
        for (int off = 16; off; off >>= 1) p += __shfl_down_sync(0xffffffffu, p, off);
        if (tx == 0) {
            int idx = 3*E_TOT + e0 + ty*8 + rr;
            if (idx < out_size) out[idx] = 1.f / (1.f + expf(-(p + b2s)));
        }
    }
}

// ---------------- kernel 5: assemble indices + bins_split --------------------
__global__ void assemble_kernel(float* __restrict__ out, int out_size) {
    int i = blockIdx.x * blockDim.x + threadIdx.x;
    if (i < E_TOT) {
        int b   = i / (N_ * KNN);
        int src = (i % (N_ * KNN)) / KNN;
        if (i*3 + 2 < out_size) {
            out[i*3 + 0] = (float)b;
            out[i*3 + 1] = (float)src;
            out[i*3 + 2] = (float)g_dst[i];
        }
    }
    if (i < B_*N_) {
        int idx = 4*E_TOT + i;
        if (idx < out_size) out[idx] = (float)g_perm[i];
    }
}

// -----------------------------------------------------------------------------
extern "C" void kernel_launch(void* const* d_in, const int* in_sizes, int n_in,
                              void* d_out, int out_size) {
    const float* inputs  = (const float*)d_in[0];
    const float* enc_w1  = (const float*)d_in[1];
    const float* enc_b1  = (const float*)d_in[2];
    const float* enc_w2  = (const float*)d_in[3];
    const float* enc_b2  = (const float*)d_in[4];
    const float* edge_w1 = (const float*)d_in[5];
    const float* edge_b1 = (const float*)d_in[6];
    const float* edge_w2 = (const float*)d_in[7];
    const float* edge_b2 = (const float*)d_in[8];
    const float* rot     = (const float*)d_in[9];
    float* out = (float*)d_out;

    size_t enc_smem = (size_t)(16384 + 16384) * sizeof(float);   // 128 KB
    cudaFuncSetAttribute(enc_kernel, cudaFuncAttributeMaxDynamicSharedMemorySize,
                         (int)enc_smem);
    enc_kernel<<<(B_*N_)/ENC_PTS, 512, enc_smem>>>(inputs, enc_w1, enc_b1,
                                                   enc_w2, enc_b2, rot);
    sort_kernel<<<B_, 256>>>();

    size_t tk_smem = 128 * 32 * sizeof(float4) + 128 * sizeof(float);
    cudaFuncSetAttribute(topk_kernel, cudaFuncAttributeMaxDynamicSharedMemorySize,
                         (int)tk_smem);
    topk_kernel<<<B_*NBINS*4, 256, tk_smem>>>();

    size_t eg_smem = (size_t)(64*ESTR + 64*DFF) * sizeof(float);   // ~162 KB
    cudaFuncSetAttribute(edge_kernel, cudaFuncAttributeMaxDynamicSharedMemorySize,
                         (int)eg_smem);
    edge_kernel<<<E_TOT/64, 256, eg_smem>>>(inputs, edge_w1, edge_b1, edge_w2, edge_b2,
                                            out, out_size);

    assemble_kernel<<<(E_TOT + 255)/256, 256>>>(out, out_size);
}

// round 3
// speedup vs baseline: 3.9620x; 2.2623x over previous
#include <cuda_runtime.h>
#include <math.h>

#define B_    4
#define N_    8000
#define FIN   256
#define DD    128
#define DFF   128
#define NBINS 16
#define BINSZ 500
#define KNN   8
#define E_TOT (B_*N_*KNN)     /* 256000 */
#define ROTC  100             /* MAX_NUM_BINS/2, row stride of rot */

// ---------------- scratch (static device globals; no allocation) -------------
__device__ float g_pe[B_*N_*DD];          // encoded points
__device__ float g_norm[B_*N_];           // squared norms of encoded points
__device__ int   g_bin[B_*N_];            // LSH bin per point
__device__ int   g_perm[B_*N_];           // stable argsort by bin == bins_split
__device__ int   g_dst[E_TOT];            // per (b,src,slot) dst, dst-sorted
__device__ float g_val[E_TOT];            // matching kernel values
__device__ float g_h12[(size_t)B_*N_*256];// [point][0:128]=X*W1a, [128:256]=X*W1b

// ---------------- packed f32x2 helpers ---------------------------------------
#define FMA2(d, a, b) asm("fma.rn.f32x2 %0, %1, %2, %0;" : "+l"(d) : "l"(a), "l"(b))

__device__ __forceinline__ unsigned long long dup2(float v) {
    unsigned iv = __float_as_uint(v);
    unsigned long long r;
    asm("mov.b64 %0, {%1, %1};" : "=l"(r) : "r"(iv), "r"(iv));
    return r;
}
__device__ __forceinline__ float f2lo(unsigned long long u) {
    return __uint_as_float((unsigned)u);
}
__device__ __forceinline__ float f2hi(unsigned long long u) {
    return __uint_as_float((unsigned)(u >> 32));
}

// ---------------- kernel 1: tiled encoder FFN + norms + LSH bin --------------
#define ENC_PTS 128
__global__ __launch_bounds__(512) void enc_kernel(
        const float* __restrict__ inputs,
        const float* __restrict__ w1, const float* __restrict__ b1,
        const float* __restrict__ w2, const float* __restrict__ b2,
        const float* __restrict__ rot) {
    extern __shared__ float sm[];
    float* r0 = sm;                 // 16384 floats: xs+ws (phase1), w2 (phase2)
    float* xs = sm;                 // [128][64]
    float* ws = sm + 8192;          // [64][128]
    float* hs = sm + 16384;         // [128][128] hidden, later reused as output
    __shared__ float b1s[DFF], b2s[DD];
    __shared__ float rots[DD * 8];
    __shared__ float ms[ENC_PTS][8];
    int tid = threadIdx.x;
    int wid = tid >> 5, tx = tid & 31;
    int n0 = blockIdx.x * ENC_PTS;

    if (tid < DFF) b1s[tid] = b1[tid];
    else if (tid < DFF + DD) b2s[tid - DFF] = b2[tid - DFF];
    for (int t = tid; t < DD * 8; t += 512) {
        int d = t >> 3, j = t & 7;
        rots[t] = rot[d * ROTC + j];
    }

    unsigned long long acc[8][2];
    #pragma unroll
    for (int rr = 0; rr < 8; ++rr) { acc[rr][0] = 0ull; acc[rr][1] = 0ull; }

    for (int kc = 0; kc < FIN; kc += 64) {
        __syncthreads();
        for (int t = tid; t < 2048; t += 512) {
            int p = t >> 4, k4 = t & 15;
            ((float4*)xs)[p * 16 + k4] =
                ((const float4*)(inputs + (size_t)(n0 + p) * FIN + kc))[k4];
        }
        for (int t = tid; t < 2048; t += 512) {
            int k = t >> 5, c4 = t & 31;
            ((float4*)ws)[k * 32 + c4] =
                ((const float4*)(w1 + (size_t)(kc + k) * DFF))[c4];
        }
        __syncthreads();
        for (int k4 = 0; k4 < 64; k4 += 4) {
            float4 e4[8];
            #pragma unroll
            for (int rr = 0; rr < 8; ++rr)
                e4[rr] = *(const float4*)&xs[(wid * 8 + rr) * 64 + k4];
            #pragma unroll
            for (int j = 0; j < 4; ++j) {
                ulonglong2 wp = *(const ulonglong2*)&ws[(k4 + j) * DFF + tx * 4];
                #pragma unroll
                for (int rr = 0; rr < 8; ++rr) {
                    float ev = (j == 0) ? e4[rr].x : (j == 1) ? e4[rr].y
                             : (j == 2) ? e4[rr].z : e4[rr].w;
                    unsigned long long ed = dup2(ev);
                    FMA2(acc[rr][0], ed, wp.x);
                    FMA2(acc[rr][1], ed, wp.y);
                }
            }
        }
    }
    #pragma unroll
    for (int rr = 0; rr < 8; ++rr) {
        int p = wid * 8 + rr;
        float h0 = f2lo(acc[rr][0]) + b1s[tx * 4 + 0];
        float h1 = f2hi(acc[rr][0]) + b1s[tx * 4 + 1];
        float h2 = f2lo(acc[rr][1]) + b1s[tx * 4 + 2];
        float h3 = f2hi(acc[rr][1]) + b1s[tx * 4 + 3];
        h0 = h0 > 0.f ? h0 : expm1f(h0);
        h1 = h1 > 0.f ? h1 : expm1f(h1);
        h2 = h2 > 0.f ? h2 : expm1f(h2);
        h3 = h3 > 0.f ? h3 : expm1f(h3);
        *(float4*)&hs[p * DFF + tx * 4] = make_float4(h0, h1, h2, h3);
    }
    __syncthreads();

    for (int t = tid; t < 4096; t += 512)
        ((float4*)r0)[t] = ((const float4*)w2)[t];
    __syncthreads();

    #pragma unroll
    for (int rr = 0; rr < 8; ++rr) { acc[rr][0] = 0ull; acc[rr][1] = 0ull; }
    for (int k4 = 0; k4 < DFF; k4 += 4) {
        float4 e4[8];
        #pragma unroll
        for (int rr = 0; rr < 8; ++rr)
            e4[rr] = *(const float4*)&hs[(wid * 8 + rr) * DFF + k4];
        #pragma unroll
        for (int j = 0; j < 4; ++j) {
            ulonglong2 wp = *(const ulonglong2*)&r0[(k4 + j) * DD + tx * 4];
            #pragma unroll
            for (int rr = 0; rr < 8; ++rr) {
                float ev = (j == 0) ? e4[rr].x : (j == 1) ? e4[rr].y
                         : (j == 2) ? e4[rr].z : e4[rr].w;
                unsigned long long ed = dup2(ev);
                FMA2(acc[rr][0], ed, wp.x);
                FMA2(acc[rr][1], ed, wp.y);
            }
        }
    }
    __syncthreads();
    #pragma unroll
    for (int rr = 0; rr < 8; ++rr) {
        int p = wid * 8 + rr;
        int n = n0 + p;
        float o0 = f2lo(acc[rr][0]) + b2s[tx * 4 + 0];
        float o1 = f2hi(acc[rr][0]) + b2s[tx * 4 + 1];
        float o2 = f2lo(acc[rr][1]) + b2s[tx * 4 + 2];
        float o3 = f2hi(acc[rr][1]) + b2s[tx * 4 + 3];
        float4 ov = make_float4(o0, o1, o2, o3);
        *(float4*)&hs[p * DD + tx * 4] = ov;
        *(float4*)&g_pe[(size_t)n * DD + tx * 4] = ov;
        float pn = o0 * o0 + o1 * o1 + o2 * o2 + o3 * o3;
        #pragma unroll
        for (int off = 16; off; off >>= 1)
            pn += __shfl_xor_sync(0xffffffffu, pn, off);
        if (tx == 0) g_norm[n] = pn;
    }
    __syncthreads();

    for (int t = tid; t < ENC_PTS * 8; t += 512) {
        int p = t >> 3, j = t & 7;
        float m = 0.f;
        #pragma unroll 8
        for (int d = 0; d < DD; ++d) m += hs[p * DD + d] * rots[d * 8 + j];
        ms[p][j] = m;
    }
    __syncthreads();
    if (tid < ENC_PTS) {
        float best = ms[tid][0]; int bi = 0;
        #pragma unroll
        for (int j = 1; j < NBINS; ++j) {
            float v = (j < 8) ? ms[tid][j] : -ms[tid][j - 8];
            if (v > best) { best = v; bi = j; }
        }
        g_bin[n0 + tid] = bi;
    }
}

// ---------------- kernel 1b: H12 = X @ [W1a | W1b] (edge-FFN precompute) -----
// Block = 128 points, 512 threads, each thread 8 rows x (4 + 4) cols.
__global__ __launch_bounds__(512) void h12_kernel(
        const float* __restrict__ inputs, const float* __restrict__ ew1) {
    extern __shared__ float sm[];
    float* xs = sm;                 // [128][64]
    float* ws = sm + 8192;          // [64][256]  cols 0:128 = W1a, 128:256 = W1b
    int tid = threadIdx.x;
    int wid = tid >> 5, tx = tid & 31;
    int n0 = blockIdx.x * 128;

    unsigned long long acc[8][4];   // 8 rows x (2 u64 H1-half + 2 u64 H2-half)
    #pragma unroll
    for (int rr = 0; rr < 8; ++rr)
        acc[rr][0] = acc[rr][1] = acc[rr][2] = acc[rr][3] = 0ull;

    for (int kc = 0; kc < FIN; kc += 64) {
        __syncthreads();
        for (int t = tid; t < 2048; t += 512) {
            int p = t >> 4, k4 = t & 15;
            ((float4*)xs)[p * 16 + k4] =
                ((const float4*)(inputs + (size_t)(n0 + p) * FIN + kc))[k4];
        }
        for (int t = tid; t < 4096; t += 512) {
            int k = t >> 6, j4 = t & 63;      // j4: float4 col group, cols j4*4
            const float* srcp = (j4 < 32)
                ? (ew1 + (size_t)(kc + k) * DFF + j4 * 4)
                : (ew1 + (size_t)(256 + kc + k) * DFF + (j4 - 32) * 4);
            ((float4*)ws)[k * 64 + j4] = *(const float4*)srcp;
        }
        __syncthreads();
        for (int k4 = 0; k4 < 64; k4 += 4) {
            float4 e4[8];
            #pragma unroll
            for (int rr = 0; rr < 8; ++rr)
                e4[rr] = *(const float4*)&xs[(wid * 8 + rr) * 64 + k4];
            #pragma unroll
            for (int j = 0; j < 4; ++j) {
                ulonglong2 wa = *(const ulonglong2*)&ws[(k4 + j) * 256 + tx * 4];
                ulonglong2 wb = *(const ulonglong2*)&ws[(k4 + j) * 256 + 128 + tx * 4];
                #pragma unroll
                for (int rr = 0; rr < 8; ++rr) {
                    float ev = (j == 0) ? e4[rr].x : (j == 1) ? e4[rr].y
                             : (j == 2) ? e4[rr].z : e4[rr].w;
                    unsigned long long ed = dup2(ev);
                    FMA2(acc[rr][0], ed, wa.x);
                    FMA2(acc[rr][1], ed, wa.y);
                    FMA2(acc[rr][2], ed, wb.x);
                    FMA2(acc[rr][3], ed, wb.y);
                }
            }
        }
    }
    #pragma unroll
    for (int rr = 0; rr < 8; ++rr) {
        size_t n = (size_t)(n0 + wid * 8 + rr);
        *(float4*)&g_h12[n * 256 + tx * 4] =
            make_float4(f2lo(acc[rr][0]), f2hi(acc[rr][0]),
                        f2lo(acc[rr][1]), f2hi(acc[rr][1]));
        *(float4*)&g_h12[n * 256 + 128 + tx * 4] =
            make_float4(f2lo(acc[rr][2]), f2hi(acc[rr][2]),
                        f2lo(acc[rr][3]), f2hi(acc[rr][3]));
    }
}

// ---------------- kernel 2: stable counting sort per batch + bins out --------
__global__ void sort_kernel(float* __restrict__ out, int out_size) {
    int b = blockIdx.x;
    __shared__ int bins[N_];
    __shared__ int cnt[NBINS];
    __shared__ int offs[NBINS];
    __shared__ int wtot[8];
    int tid = threadIdx.x;         // 256
    int wid = tid >> 5, lane = tid & 31;
    for (int i = tid; i < N_; i += 256) bins[i] = g_bin[b*N_ + i];
    if (tid < NBINS) cnt[tid] = 0;
    __syncthreads();
    for (int i = tid; i < N_; i += 256) atomicAdd(&cnt[bins[i]], 1);
    __syncthreads();
    if (tid == 0) { int s = 0; for (int k = 0; k < NBINS; ++k) { offs[k] = s; s += cnt[k]; } }
    __syncthreads();
    for (int bin = 0; bin < NBINS; ++bin) {
        int base = offs[bin];
        for (int c0 = 0; c0 < N_; c0 += 256) {
            int i = c0 + tid;
            int flag = (i < N_ && bins[i] == bin) ? 1 : 0;
            unsigned m = __ballot_sync(0xffffffffu, flag);
            int wpre = __popc(m & ((1u << lane) - 1u));
            if (lane == 0) wtot[wid] = __popc(m);
            __syncthreads();
            int woff = 0;
            for (int w = 0; w < wid; ++w) woff += wtot[w];
            int tot = 0;
            for (int w = 0; w < 8; ++w) tot += wtot[w];
            if (flag) g_perm[b*N_ + base + woff + wpre] = i;
            base += tot;
            __syncthreads();
        }
    }
    __syncthreads();
    for (int i = tid; i < N_; i += 256) {
        int idx = 4*E_TOT + b*N_ + i;
        if (idx < out_size) out[idx] = (float)g_perm[b*N_ + i];
    }
}

// ---------------- kernel 3: per-(batch,bin,rowgroup) top-8 by min d2 ---------
// 512 blocks = 64 (b,bin) x 8 row groups. Selection on clamped d2 (monotone
// with dm); exp/sqrt deferred to the 8 winners.
__device__ __forceinline__ bool better(float ad2, int ai, float bd2, int bi) {
    return (ad2 < bd2) || (ad2 == bd2 && ai < bi);
}

__global__ void topk_kernel() {
    int bb = blockIdx.x;
    int rg = bb & 7;
    int bbin = bb >> 3;
    int b = bbin / NBINS, bin = bbin % NBINS;
    extern __shared__ float smx[];
    float4* colbuf = (float4*)smx;                 // [128 cols][32 float4]
    float* cnorm = smx + 128 * 32 * 4;             // [128]
    const int* perm = g_perm + b*N_ + bin*BINSZ;
    const float* pe = g_pe + (size_t)b*N_*DD;
    int tid = threadIdx.x;
    int rl = tid >> 2, l4 = tid & 3;               // 64 row slots, 4 lanes/row
    int rbase = rg * 63;
    int rcount = min(63, BINSZ - rbase);           // 63 (rg<7) or 59 (rg==7)

    bool rvalid = rl < rcount;
    int row = rbase + (rvalid ? rl : 0);
    int rsrc = perm[row];
    ulonglong2 rp[8];
    {
        const ulonglong2* prow = (const ulonglong2*)(pe + (size_t)rsrc*DD) + l4*8;
        #pragma unroll
        for (int kk = 0; kk < 8; ++kk) rp[kk] = prow[kk];
    }
    float rn = g_norm[b*N_ + rsrc];
    float tv[KNN]; int ti[KNN];
    #pragma unroll
    for (int s = 0; s < KNN; ++s) { tv[s] = 3.0e38f; ti[s] = 1 << 30; }

    for (int cc = 0; cc < BINSZ; cc += 128) {
        int csize = min(128, BINSZ - cc);
        __syncthreads();
        for (int t = tid; t < csize*32; t += 256) {
            int c = t >> 5, k = t & 31;
            colbuf[c*32 + k] = ((const float4*)(pe + (size_t)perm[cc + c]*DD))[k];
        }
        for (int t = tid; t < csize; t += 256)
            cnorm[t] = g_norm[b*N_ + perm[cc + t]];
        __syncthreads();
        for (int c = 0; c < csize; ++c) {
            unsigned long long a0 = 0ull, a1 = 0ull;
            #pragma unroll
            for (int kk = 0; kk < 8; ++kk) {
                int ke = (kk + 2*l4) & 7;                     // bank stagger
                ulonglong2 cp = *(const ulonglong2*)&colbuf[c*32 + l4*8 + ke];
                FMA2(a0, rp[ke].x, cp.x);
                FMA2(a1, rp[ke].y, cp.y);
            }
            float part = f2lo(a0) + f2hi(a0) + f2lo(a1) + f2hi(a1);
            part += __shfl_down_sync(0xffffffffu, part, 2, 4);
            part += __shfl_down_sync(0xffffffffu, part, 1, 4);
            if (l4 == 0) {
                float d2 = fmaxf((rn - 2.0f * part) + cnorm[c], 1e-6f);
                int gi = cc + c;
                if (better(d2, gi, tv[KNN-1], ti[KNN-1])) {
                    tv[KNN-1] = d2; ti[KNN-1] = gi;
                    #pragma unroll
                    for (int s = KNN-1; s > 0; --s) {
                        if (better(tv[s], ti[s], tv[s-1], ti[s-1])) {
                            float fv = tv[s]; tv[s] = tv[s-1]; tv[s-1] = fv;
                            int   fi = ti[s]; ti[s] = ti[s-1]; ti[s-1] = fi;
                        }
                    }
                }
            }
        }
    }
    if (rvalid && l4 == 0) {
        int dsts[KNN]; float vals[KNN];
        #pragma unroll
        for (int s = 0; s < KNN; ++s) {
            dsts[s] = perm[ti[s]];
            vals[s] = expf(-0.1f * sqrtf(tv[s]));
        }
        #pragma unroll
        for (int i = 1; i < KNN; ++i) {
            int dk = dsts[i]; float vk = vals[i]; int j = i - 1;
            while (j >= 0 && dsts[j] > dk) {
                dsts[j+1] = dsts[j]; vals[j+1] = vals[j]; --j;
            }
            dsts[j+1] = dk; vals[j+1] = vk;
        }
        size_t base = ((size_t)b*N_ + rsrc) * KNN;
        #pragma unroll
        for (int s = 0; s < KNN; ++s) { g_dst[base+s] = dsts[s]; g_val[base+s] = vals[s]; }
    }
}

// ---------------- kernel 4: edge epilogue (gather H1/H2 + elu + dot + sig) ---
// One warp per source point (8 edges); lane j handles features 4j..4j+3.
__global__ __launch_bounds__(256) void edge_kernel(
        const float* __restrict__ ew1, const float* __restrict__ b1,
        const float* __restrict__ w2, const float* __restrict__ b2v,
        float* __restrict__ out, int out_size) {
    int wid = threadIdx.x >> 5, lane = threadIdx.x & 31;
    int p = blockIdx.x * 8 + wid;           // 0..31999
    int b = p / N_;
    int src = p % N_;
    float4 w1c = *(const float4*)&ew1[(size_t)512 * DFF + lane * 4];
    float4 b14 = *(const float4*)&b1[lane * 4];
    float4 w24 = *(const float4*)&w2[lane * 4];
    float b2s = b2v[0];
    float4 h1 = *(const float4*)&g_h12[(size_t)p * 256 + lane * 4];
    float bx = h1.x + b14.x, by = h1.y + b14.y;
    float bz = h1.z + b14.z, bw = h1.w + b14.w;
    size_t ebase = (size_t)p * KNN;
    #pragma unroll
    for (int i = 0; i < KNN; ++i) {
        int dst = g_dst[ebase + i];
        float val = g_val[ebase + i];
        float4 h2 = *(const float4*)&g_h12[((size_t)(b*N_ + dst)) * 256 + 128 + lane * 4];
        float x0 = bx + h2.x + val * w1c.x;
        float x1 = by + h2.y + val * w1c.y;
        float x2 = bz + h2.z + val * w1c.z;
        float x3 = bw + h2.w + val * w1c.w;
        x0 = x0 > 0.f ? x0 : expm1f(x0);
        x1 = x1 > 0.f ? x1 : expm1f(x1);
        x2 = x2 > 0.f ? x2 : expm1f(x2);
        x3 = x3 > 0.f ? x3 : expm1f(x3);
        float s = x0 * w24.x + x1 * w24.y + x2 * w24.z + x3 * w24.w;
        #pragma unroll
        for (int off = 16; off; off >>= 1) s += __shfl_down_sync(0xffffffffu, s, off);
        if (lane == 0) {
            int eid = (int)ebase + i;
            if (3*E_TOT + eid < out_size)
                out[3*E_TOT + eid] = 1.f / (1.f + expf(-(s + b2s)));
            if (eid*3 + 2 < out_size) {
                out[eid*3 + 0] = (float)b;
                out[eid*3 + 1] = (float)src;
                out[eid*3 + 2] = (float)dst;
            }
        }
    }
}

// -----------------------------------------------------------------------------
extern "C" void kernel_launch(void* const* d_in, const int* in_sizes, int n_in,
                              void* d_out, int out_size) {
    const float* inputs  = (const float*)d_in[0];
    const float* enc_w1  = (const float*)d_in[1];
    const float* enc_b1  = (const float*)d_in[2];
    const float* enc_w2  = (const float*)d_in[3];
    const float* enc_b2  = (const float*)d_in[4];
    const float* edge_w1 = (const float*)d_in[5];
    const float* edge_b1 = (const float*)d_in[6];
    const float* edge_w2 = (const float*)d_in[7];
    const float* edge_b2 = (const float*)d_in[8];
    const float* rot     = (const float*)d_in[9];
    float* out = (float*)d_out;

    size_t enc_smem = (size_t)(16384 + 16384) * sizeof(float);   // 128 KB
    cudaFuncSetAttribute(enc_kernel, cudaFuncAttributeMaxDynamicSharedMemorySize,
                         (int)enc_smem);
    enc_kernel<<<(B_*N_)/ENC_PTS, 512, enc_smem>>>(inputs, enc_w1, enc_b1,
                                                   enc_w2, enc_b2, rot);

    size_t h12_smem = (size_t)(8192 + 16384) * sizeof(float);    // 96 KB
    cudaFuncSetAttribute(h12_kernel, cudaFuncAttributeMaxDynamicSharedMemorySize,
                         (int)h12_smem);
    h12_kernel<<<(B_*N_)/128, 512, h12_smem>>>(inputs, edge_w1);

    sort_kernel<<<B_, 256>>>(out, out_size);

    size_t tk_smem = 128 * 32 * sizeof(float4) + 128 * sizeof(float);
    cudaFuncSetAttribute(topk_kernel, cudaFuncAttributeMaxDynamicSharedMemorySize,
                         (int)tk_smem);
    topk_kernel<<<B_*NBINS*8, 256, tk_smem>>>();

    edge_kernel<<<(B_*N_)/8, 256>>>(edge_w1, edge_b1, edge_w2, edge_b2,
                                    out, out_size);
}

// round 4
// speedup vs baseline: 4.4918x; 1.1337x over previous
#include <cuda_runtime.h>
#include <math.h>

#define B_    4
#define N_    8000
#define FIN   256
#define DD    128
#define DFF   128
#define NBINS 16
#define BINSZ 500
#define KNN   8
#define E_TOT (B_*N_*KNN)     /* 256000 */
#define ROTC  100             /* MAX_NUM_BINS/2, row stride of rot */

// ---------------- scratch (static device globals; no allocation) -------------
__device__ float g_pe[B_*N_*DD];          // encoded points
__device__ float g_norm[B_*N_];           // squared norms of encoded points
__device__ int   g_bin[B_*N_];            // LSH bin per point
__device__ int   g_perm[B_*N_];           // stable argsort by bin == bins_split
__device__ int   g_dst[E_TOT];            // per (b,src,slot) dst, dst-sorted
__device__ float g_val[E_TOT];            // matching kernel values
__device__ float g_h12[(size_t)B_*N_*256];// [point][0:128]=X*W1a, [128:256]=X*W1b

// ---------------- packed f32x2 helpers ---------------------------------------
#define FMA2(d, a, b) asm("fma.rn.f32x2 %0, %1, %2, %0;" : "+l"(d) : "l"(a), "l"(b))

__device__ __forceinline__ unsigned long long dup2(float v) {
    unsigned iv = __float_as_uint(v);
    unsigned long long r;
    asm("mov.b64 %0, {%1, %1};" : "=l"(r) : "r"(iv), "r"(iv));
    return r;
}
__device__ __forceinline__ float f2lo(unsigned long long u) {
    return __uint_as_float((unsigned)u);
}
__device__ __forceinline__ float f2hi(unsigned long long u) {
    return __uint_as_float((unsigned)(u >> 32));
}

// ---------------- kernel 1: tiled encoder FFN + norms + LSH bin --------------
#define ENC_PTS 128
__global__ __launch_bounds__(512) void enc_kernel(
        const float* __restrict__ inputs,
        const float* __restrict__ w1, const float* __restrict__ b1,
        const float* __restrict__ w2, const float* __restrict__ b2,
        const float* __restrict__ rot) {
    extern __shared__ float sm[];
    float* r0 = sm;                 // 16384 floats: xs+ws (phase1), w2 (phase2)
    float* xs = sm;                 // [128][64]
    float* ws = sm + 8192;          // [64][128]
    float* hs = sm + 16384;         // [128][128] hidden, later reused as output
    __shared__ float b1s[DFF], b2s[DD];
    __shared__ float rots[DD * 8];
    __shared__ float ms[ENC_PTS][8];
    int tid = threadIdx.x;
    int wid = tid >> 5, tx = tid & 31;
    int n0 = blockIdx.x * ENC_PTS;

    if (tid < DFF) b1s[tid] = b1[tid];
    else if (tid < DFF + DD) b2s[tid - DFF] = b2[tid - DFF];
    for (int t = tid; t < DD * 8; t += 512) {
        int d = t >> 3, j = t & 7;
        rots[t] = rot[d * ROTC + j];
    }

    unsigned long long acc[8][2];
    #pragma unroll
    for (int rr = 0; rr < 8; ++rr) { acc[rr][0] = 0ull; acc[rr][1] = 0ull; }

    for (int kc = 0; kc < FIN; kc += 64) {
        __syncthreads();
        for (int t = tid; t < 2048; t += 512) {
            int p = t >> 4, k4 = t & 15;
            ((float4*)xs)[p * 16 + k4] =
                ((const float4*)(inputs + (size_t)(n0 + p) * FIN + kc))[k4];
        }
        for (int t = tid; t < 2048; t += 512) {
            int k = t >> 5, c4 = t & 31;
            ((float4*)ws)[k * 32 + c4] =
                ((const float4*)(w1 + (size_t)(kc + k) * DFF))[c4];
        }
        __syncthreads();
        for (int k4 = 0; k4 < 64; k4 += 4) {
            float4 e4[8];
            #pragma unroll
            for (int rr = 0; rr < 8; ++rr)
                e4[rr] = *(const float4*)&xs[(wid * 8 + rr) * 64 + k4];
            #pragma unroll
            for (int j = 0; j < 4; ++j) {
                ulonglong2 wp = *(const ulonglong2*)&ws[(k4 + j) * DFF + tx * 4];
                #pragma unroll
                for (int rr = 0; rr < 8; ++rr) {
                    float ev = (j == 0) ? e4[rr].x : (j == 1) ? e4[rr].y
                             : (j == 2) ? e4[rr].z : e4[rr].w;
                    unsigned long long ed = dup2(ev);
                    FMA2(acc[rr][0], ed, wp.x);
                    FMA2(acc[rr][1], ed, wp.y);
                }
            }
        }
    }
    #pragma unroll
    for (int rr = 0; rr < 8; ++rr) {
        int p = wid * 8 + rr;
        float h0 = f2lo(acc[rr][0]) + b1s[tx * 4 + 0];
        float h1 = f2hi(acc[rr][0]) + b1s[tx * 4 + 1];
        float h2 = f2lo(acc[rr][1]) + b1s[tx * 4 + 2];
        float h3 = f2hi(acc[rr][1]) + b1s[tx * 4 + 3];
        h0 = h0 > 0.f ? h0 : expm1f(h0);
        h1 = h1 > 0.f ? h1 : expm1f(h1);
        h2 = h2 > 0.f ? h2 : expm1f(h2);
        h3 = h3 > 0.f ? h3 : expm1f(h3);
        *(float4*)&hs[p * DFF + tx * 4] = make_float4(h0, h1, h2, h3);
    }
    __syncthreads();

    for (int t = tid; t < 4096; t += 512)
        ((float4*)r0)[t] = ((const float4*)w2)[t];
    __syncthreads();

    #pragma unroll
    for (int rr = 0; rr < 8; ++rr) { acc[rr][0] = 0ull; acc[rr][1] = 0ull; }
    for (int k4 = 0; k4 < DFF; k4 += 4) {
        float4 e4[8];
        #pragma unroll
        for (int rr = 0; rr < 8; ++rr)
            e4[rr] = *(const float4*)&hs[(wid * 8 + rr) * DFF + k4];
        #pragma unroll
        for (int j = 0; j < 4; ++j) {
            ulonglong2 wp = *(const ulonglong2*)&r0[(k4 + j) * DD + tx * 4];
            #pragma unroll
            for (int rr = 0; rr < 8; ++rr) {
                float ev = (j == 0) ? e4[rr].x : (j == 1) ? e4[rr].y
                         : (j == 2) ? e4[rr].z : e4[rr].w;
                unsigned long long ed = dup2(ev);
                FMA2(acc[rr][0], ed, wp.x);
                FMA2(acc[rr][1], ed, wp.y);
            }
        }
    }
    __syncthreads();
    #pragma unroll
    for (int rr = 0; rr < 8; ++rr) {
        int p = wid * 8 + rr;
        int n = n0 + p;
        float o0 = f2lo(acc[rr][0]) + b2s[tx * 4 + 0];
        float o1 = f2hi(acc[rr][0]) + b2s[tx * 4 + 1];
        float o2 = f2lo(acc[rr][1]) + b2s[tx * 4 + 2];
        float o3 = f2hi(acc[rr][1]) + b2s[tx * 4 + 3];
        float4 ov = make_float4(o0, o1, o2, o3);
        *(float4*)&hs[p * DD + tx * 4] = ov;
        *(float4*)&g_pe[(size_t)n * DD + tx * 4] = ov;
        float pn = o0 * o0 + o1 * o1 + o2 * o2 + o3 * o3;
        #pragma unroll
        for (int off = 16; off; off >>= 1)
            pn += __shfl_xor_sync(0xffffffffu, pn, off);
        if (tx == 0) g_norm[n] = pn;
    }
    __syncthreads();

    for (int t = tid; t < ENC_PTS * 8; t += 512) {
        int p = t >> 3, j = t & 7;
        float m = 0.f;
        #pragma unroll 8
        for (int d = 0; d < DD; ++d) m += hs[p * DD + d] * rots[d * 8 + j];
        ms[p][j] = m;
    }
    __syncthreads();
    if (tid < ENC_PTS) {
        float best = ms[tid][0]; int bi = 0;
        #pragma unroll
        for (int j = 1; j < NBINS; ++j) {
            float v = (j < 8) ? ms[tid][j] : -ms[tid][j - 8];
            if (v > best) { best = v; bi = j; }
        }
        g_bin[n0 + tid] = bi;
    }
}

// ---------------- kernel 1b: H12 = X @ [W1a | W1b] (edge-FFN precompute) -----
__global__ __launch_bounds__(512) void h12_kernel(
        const float* __restrict__ inputs, const float* __restrict__ ew1) {
    extern __shared__ float sm[];
    float* xs = sm;                 // [128][64]
    float* ws = sm + 8192;          // [64][256]
    int tid = threadIdx.x;
    int wid = tid >> 5, tx = tid & 31;
    int n0 = blockIdx.x * 128;

    unsigned long long acc[8][4];
    #pragma unroll
    for (int rr = 0; rr < 8; ++rr)
        acc[rr][0] = acc[rr][1] = acc[rr][2] = acc[rr][3] = 0ull;

    for (int kc = 0; kc < FIN; kc += 64) {
        __syncthreads();
        for (int t = tid; t < 2048; t += 512) {
            int p = t >> 4, k4 = t & 15;
            ((float4*)xs)[p * 16 + k4] =
                ((const float4*)(inputs + (size_t)(n0 + p) * FIN + kc))[k4];
        }
        for (int t = tid; t < 4096; t += 512) {
            int k = t >> 6, j4 = t & 63;
            const float* srcp = (j4 < 32)
                ? (ew1 + (size_t)(kc + k) * DFF + j4 * 4)
                : (ew1 + (size_t)(256 + kc + k) * DFF + (j4 - 32) * 4);
            ((float4*)ws)[k * 64 + j4] = *(const float4*)srcp;
        }
        __syncthreads();
        for (int k4 = 0; k4 < 64; k4 += 4) {
            float4 e4[8];
            #pragma unroll
            for (int rr = 0; rr < 8; ++rr)
                e4[rr] = *(const float4*)&xs[(wid * 8 + rr) * 64 + k4];
            #pragma unroll
            for (int j = 0; j < 4; ++j) {
                ulonglong2 wa = *(const ulonglong2*)&ws[(k4 + j) * 256 + tx * 4];
                ulonglong2 wb = *(const ulonglong2*)&ws[(k4 + j) * 256 + 128 + tx * 4];
                #pragma unroll
                for (int rr = 0; rr < 8; ++rr) {
                    float ev = (j == 0) ? e4[rr].x : (j == 1) ? e4[rr].y
                             : (j == 2) ? e4[rr].z : e4[rr].w;
                    unsigned long long ed = dup2(ev);
                    FMA2(acc[rr][0], ed, wa.x);
                    FMA2(acc[rr][1], ed, wa.y);
                    FMA2(acc[rr][2], ed, wb.x);
                    FMA2(acc[rr][3], ed, wb.y);
                }
            }
        }
    }
    #pragma unroll
    for (int rr = 0; rr < 8; ++rr) {
        size_t n = (size_t)(n0 + wid * 8 + rr);
        *(float4*)&g_h12[n * 256 + tx * 4] =
            make_float4(f2lo(acc[rr][0]), f2hi(acc[rr][0]),
                        f2lo(acc[rr][1]), f2hi(acc[rr][1]));
        *(float4*)&g_h12[n * 256 + 128 + tx * 4] =
            make_float4(f2lo(acc[rr][2]), f2hi(acc[rr][2]),
                        f2lo(acc[rr][3]), f2hi(acc[rr][3]));
    }
}

// ---------------- kernel 2: stable counting sort (match_any) + bins out ------
__global__ __launch_bounds__(256) void sort_kernel(float* __restrict__ out,
                                                   int out_size) {
    int b = blockIdx.x;
    __shared__ int bins[N_];
    __shared__ int cnt[NBINS];
    __shared__ int basebin[NBINS];
    __shared__ int wcnt[8][NBINS];
    int tid = threadIdx.x, wid = tid >> 5, lane = tid & 31;
    unsigned ltmask = (1u << lane) - 1u;
    for (int i = tid; i < N_; i += 256) bins[i] = g_bin[b*N_ + i];
    if (tid < NBINS) cnt[tid] = 0;
    __syncthreads();
    // histogram (warp-aggregated atomics)
    for (int i = tid; i < N_; i += 256) {
        int bi = bins[i];
        unsigned m = __match_any_sync(0xffffffffu, bi);
        if ((m & ltmask) == 0) atomicAdd(&cnt[bi], __popc(m));
    }
    __syncthreads();
    if (tid == 0) {
        int s = 0;
        for (int k = 0; k < NBINS; ++k) { basebin[k] = s; s += cnt[k]; }
    }
    __syncthreads();
    // stable scatter, 256 elements per chunk
    for (int c0 = 0; c0 < N_; c0 += 256) {
        int i = c0 + tid;
        int bi = (i < N_) ? bins[i] : -1;
        unsigned m = __match_any_sync(0xffffffffu, bi);
        int wrank = __popc(m & ltmask);
        if (tid < 128) wcnt[tid >> 4][tid & 15] = 0;
        __syncthreads();
        if ((m & ltmask) == 0 && bi >= 0) wcnt[wid][bi] = __popc(m);
        __syncthreads();
        if (bi >= 0) {
            int off = basebin[bi];
            #pragma unroll
            for (int w = 0; w < 8; ++w) if (w < wid) off += wcnt[w][bi];
            g_perm[b*N_ + off + wrank] = i;
        }
        __syncthreads();
        if (tid < NBINS) {
            int t = 0;
            #pragma unroll
            for (int w = 0; w < 8; ++w) t += wcnt[w][tid];
            basebin[tid] += t;
        }
        __syncthreads();
    }
    for (int i = tid; i < N_; i += 256) {
        int idx = 4*E_TOT + b*N_ + i;
        if (idx < out_size) out[idx] = (float)g_perm[b*N_ + i];
    }
}

// ---------------- kernel 3: per-(batch,bin,rowgroup) top-8 by min d2 ---------
// 512 blocks = 64 (b,bin) x 8 row groups. 2-column batches, 8 accumulators.
#define TK_COLS 64
__device__ __forceinline__ bool better(float ad2, int ai, float bd2, int bi) {
    return (ad2 < bd2) || (ad2 == bd2 && ai < bi);
}

__global__ __launch_bounds__(256, 3) void topk_kernel() {
    int bb = blockIdx.x;
    int rg = bb & 7;
    int bbin = bb >> 3;
    int b = bbin / NBINS, bin = bbin % NBINS;
    extern __shared__ float smx[];
    float4* colbuf = (float4*)smx;                 // [64 cols][32 float4] 32KB
    float* cnorm = smx + TK_COLS * 32 * 4;         // [64]
    const int* perm = g_perm + b*N_ + bin*BINSZ;
    const float* pe = g_pe + (size_t)b*N_*DD;
    int tid = threadIdx.x;
    int rl = tid >> 2, l4 = tid & 3;
    int rbase = rg * 63;
    int rcount = min(63, BINSZ - rbase);

    bool rvalid = rl < rcount;
    int row = rbase + (rvalid ? rl : 0);
    int rsrc = perm[row];
    ulonglong2 rp[8];
    {
        const ulonglong2* prow = (const ulonglong2*)(pe + (size_t)rsrc*DD) + l4*8;
        #pragma unroll
        for (int kk = 0; kk < 8; ++kk) rp[kk] = prow[kk];
    }
    float rn = g_norm[b*N_ + rsrc];
    float tv[KNN]; int ti[KNN];
    #pragma unroll
    for (int s = 0; s < KNN; ++s) { tv[s] = 3.0e38f; ti[s] = 1 << 30; }

    for (int cc = 0; cc < BINSZ; cc += TK_COLS) {
        int csize = min(TK_COLS, BINSZ - cc);          // 64 or 52 (both even)
        __syncthreads();
        for (int t = tid; t < csize*32; t += 256) {
            int c = t >> 5, k = t & 31;
            colbuf[c*32 + k] = ((const float4*)(pe + (size_t)perm[cc + c]*DD))[k];
        }
        for (int t = tid; t < csize; t += 256)
            cnorm[t] = g_norm[b*N_ + perm[cc + t]];
        __syncthreads();
        for (int c = 0; c < csize; c += 2) {
            unsigned long long a0=0ull, a1=0ull, a2=0ull, a3=0ull;
            unsigned long long e0=0ull, e1=0ull, e2=0ull, e3=0ull;
            const ulonglong2* col0 = (const ulonglong2*)&colbuf[c*32 + l4*8];
            const ulonglong2* col1 = (const ulonglong2*)&colbuf[(c+1)*32 + l4*8];
            #pragma unroll
            for (int kk = 0; kk < 4; ++kk) {
                int ke0 = (2*kk + 2*l4) & 7;
                int ke1 = (2*kk + 1 + 2*l4) & 7;
                ulonglong2 c00 = col0[ke0], c01 = col0[ke1];
                ulonglong2 c10 = col1[ke0], c11 = col1[ke1];
                FMA2(a0, rp[ke0].x, c00.x); FMA2(a1, rp[ke0].y, c00.y);
                FMA2(a2, rp[ke1].x, c01.x); FMA2(a3, rp[ke1].y, c01.y);
                FMA2(e0, rp[ke0].x, c10.x); FMA2(e1, rp[ke0].y, c10.y);
                FMA2(e2, rp[ke1].x, c11.x); FMA2(e3, rp[ke1].y, c11.y);
            }
            float p0 = (f2lo(a0) + f2hi(a0)) + (f2lo(a1) + f2hi(a1))
                     + (f2lo(a2) + f2hi(a2)) + (f2lo(a3) + f2hi(a3));
            float p1 = (f2lo(e0) + f2hi(e0)) + (f2lo(e1) + f2hi(e1))
                     + (f2lo(e2) + f2hi(e2)) + (f2lo(e3) + f2hi(e3));
            p0 += __shfl_down_sync(0xffffffffu, p0, 2, 4);
            p0 += __shfl_down_sync(0xffffffffu, p0, 1, 4);
            p1 += __shfl_down_sync(0xffffffffu, p1, 2, 4);
            p1 += __shfl_down_sync(0xffffffffu, p1, 1, 4);
            if (l4 == 0) {
                float d20 = fmaxf((rn - 2.0f * p0) + cnorm[c], 1e-6f);
                float d21 = fmaxf((rn - 2.0f * p1) + cnorm[c+1], 1e-6f);
                int gi0 = cc + c, gi1 = cc + c + 1;
                if (better(d20, gi0, tv[KNN-1], ti[KNN-1])) {
                    tv[KNN-1] = d20; ti[KNN-1] = gi0;
                    #pragma unroll
                    for (int s = KNN-1; s > 0; --s) {
                        if (better(tv[s], ti[s], tv[s-1], ti[s-1])) {
                            float fv = tv[s]; tv[s] = tv[s-1]; tv[s-1] = fv;
                            int   fi = ti[s]; ti[s] = ti[s-1]; ti[s-1] = fi;
                        }
                    }
                }
                if (better(d21, gi1, tv[KNN-1], ti[KNN-1])) {
                    tv[KNN-1] = d21; ti[KNN-1] = gi1;
                    #pragma unroll
                    for (int s = KNN-1; s > 0; --s) {
                        if (better(tv[s], ti[s], tv[s-1], ti[s-1])) {
                            float fv = tv[s]; tv[s] = tv[s-1]; tv[s-1] = fv;
                            int   fi = ti[s]; ti[s] = ti[s-1]; ti[s-1] = fi;
                        }
                    }
                }
            }
        }
    }
    if (rvalid && l4 == 0) {
        int dsts[KNN]; float vals[KNN];
        #pragma unroll
        for (int s = 0; s < KNN; ++s) {
            dsts[s] = perm[ti[s]];
            vals[s] = expf(-0.1f * sqrtf(tv[s]));
        }
        #pragma unroll
        for (int i = 1; i < KNN; ++i) {
            int dk = dsts[i]; float vk = vals[i]; int j = i - 1;
            while (j >= 0 && dsts[j] > dk) {
                dsts[j+1] = dsts[j]; vals[j+1] = vals[j]; --j;
            }
            dsts[j+1] = dk; vals[j+1] = vk;
        }
        size_t base = ((size_t)b*N_ + rsrc) * KNN;
        #pragma unroll
        for (int s = 0; s < KNN; ++s) { g_dst[base+s] = dsts[s]; g_val[base+s] = vals[s]; }
    }
}

// ---------------- kernel 4: edge epilogue (gather H1/H2 + elu + dot + sig) ---
__global__ __launch_bounds__(256) void edge_kernel(
        const float* __restrict__ ew1, const float* __restrict__ b1,
        const float* __restrict__ w2, const float* __restrict__ b2v,
        float* __restrict__ out, int out_size) {
    int wid = threadIdx.x >> 5, lane = threadIdx.x & 31;
    int p = blockIdx.x * 8 + wid;           // 0..31999
    int b = p / N_;
    int src = p % N_;
    float4 w1c = *(const float4*)&ew1[(size_t)512 * DFF + lane * 4];
    float4 b14 = *(const float4*)&b1[lane * 4];
    float4 w24 = *(const float4*)&w2[lane * 4];
    float b2s = b2v[0];
    float4 h1 = *(const float4*)&g_h12[(size_t)p * 256 + lane * 4];
    float bx = h1.x + b14.x, by = h1.y + b14.y;
    float bz = h1.z + b14.z, bw = h1.w + b14.w;
    size_t ebase = (size_t)p * KNN;
    #pragma unroll
    for (int i = 0; i < KNN; ++i) {
        int dst = g_dst[ebase + i];
        float val = g_val[ebase + i];
        float4 h2 = *(const float4*)&g_h12[((size_t)(b*N_ + dst)) * 256 + 128 + lane * 4];
        float x0 = bx + h2.x + val * w1c.x;
        float x1 = by + h2.y + val * w1c.y;
        float x2 = bz + h2.z + val * w1c.z;
        float x3 = bw + h2.w + val * w1c.w;
        x0 = x0 > 0.f ? x0 : expm1f(x0);
        x1 = x1 > 0.f ? x1 : expm1f(x1);
        x2 = x2 > 0.f ? x2 : expm1f(x2);
        x3 = x3 > 0.f ? x3 : expm1f(x3);
        float s = x0 * w24.x + x1 * w24.y + x2 * w24.z + x3 * w24.w;
        #pragma unroll
        for (int off = 16; off; off >>= 1) s += __shfl_down_sync(0xffffffffu, s, off);
        if (lane == 0) {
            int eid = (int)ebase + i;
            if (3*E_TOT + eid < out_size)
                out[3*E_TOT + eid] = 1.f / (1.f + expf(-(s + b2s)));
            if (eid*3 + 2 < out_size) {
                out[eid*3 + 0] = (float)b;
                out[eid*3 + 1] = (float)src;
                out[eid*3 + 2] = (float)dst;
            }
        }
    }
}

// -----------------------------------------------------------------------------
extern "C" void kernel_launch(void* const* d_in, const int* in_sizes, int n_in,
                              void* d_out, int out_size) {
    const float* inputs  = (const float*)d_in[0];
    const float* enc_w1  = (const float*)d_in[1];
    const float* enc_b1  = (const float*)d_in[2];
    const float* enc_w2  = (const float*)d_in[3];
    const float* enc_b2  = (const float*)d_in[4];
    const float* edge_w1 = (const float*)d_in[5];
    const float* edge_b1 = (const float*)d_in[6];
    const float* edge_w2 = (const float*)d_in[7];
    const float* edge_b2 = (const float*)d_in[8];
    const float* rot     = (const float*)d_in[9];
    float* out = (float*)d_out;

    size_t enc_smem = (size_t)(16384 + 16384) * sizeof(float);   // 128 KB
    cudaFuncSetAttribute(enc_kernel, cudaFuncAttributeMaxDynamicSharedMemorySize,
                         (int)enc_smem);
    enc_kernel<<<(B_*N_)/ENC_PTS, 512, enc_smem>>>(inputs, enc_w1, enc_b1,
                                                   enc_w2, enc_b2, rot);

    size_t h12_smem = (size_t)(8192 + 16384) * sizeof(float);    // 96 KB
    cudaFuncSetAttribute(h12_kernel, cudaFuncAttributeMaxDynamicSharedMemorySize,
                         (int)h12_smem);
    h12_kernel<<<(B_*N_)/128, 512, h12_smem>>>(inputs, edge_w1);

    sort_kernel<<<B_, 256>>>(out, out_size);

    size_t tk_smem = (size_t)(TK_COLS * 32 * 4 + TK_COLS) * sizeof(float);
    cudaFuncSetAttribute(topk_kernel, cudaFuncAttributeMaxDynamicSharedMemorySize,
                         (int)tk_smem);
    topk_kernel<<<B_*NBINS*8, 256, tk_smem>>>();

    edge_kernel<<<(B_*N_)/8, 256>>>(edge_w1, edge_b1, edge_w2, edge_b2,
                                    out, out_size);
}

// round 5
// speedup vs baseline: 4.6644x; 1.0384x over previous
#include <cuda_runtime.h>
#include <math.h>

#define B_    4
#define N_    8000
#define FIN   256
#define DD    128
#define DFF   128
#define NBINS 16
#define BINSZ 500
#define KNN   8
#define E_TOT (B_*N_*KNN)     /* 256000 */
#define ROTC  100             /* MAX_NUM_BINS/2, row stride of rot */

// ---------------- scratch (static device globals; no allocation) -------------
__device__ float g_pe[B_*N_*DD];          // encoded points
__device__ float g_norm[B_*N_];           // squared norms of encoded points
__device__ int   g_bin[B_*N_];            // LSH bin per point
__device__ int   g_perm[B_*N_];           // stable argsort by bin == bins_split
__device__ int   g_dst[E_TOT];            // per (b,src,slot) dst, dst-sorted
__device__ float g_val[E_TOT];            // matching kernel values
__device__ float g_h12[(size_t)B_*N_*256];// [point][0:128]=X*W1a, [128:256]=X*W1b

// ---------------- packed f32x2 helpers ---------------------------------------
#define FMA2(d, a, b) asm("fma.rn.f32x2 %0, %1, %2, %0;" : "+l"(d) : "l"(a), "l"(b))

__device__ __forceinline__ unsigned long long dup2(float v) {
    unsigned iv = __float_as_uint(v);
    unsigned long long r;
    asm("mov.b64 %0, {%1, %1};" : "=l"(r) : "r"(iv), "r"(iv));
    return r;
}
__device__ __forceinline__ float f2lo(unsigned long long u) {
    return __uint_as_float((unsigned)u);
}
__device__ __forceinline__ float f2hi(unsigned long long u) {
    return __uint_as_float((unsigned)(u >> 32));
}

// ---------------- kernel 1: tiled encoder FFN + norms + LSH bin --------------
#define ENC_PTS 128
__global__ __launch_bounds__(512) void enc_kernel(
        const float* __restrict__ inputs,
        const float* __restrict__ w1, const float* __restrict__ b1,
        const float* __restrict__ w2, const float* __restrict__ b2,
        const float* __restrict__ rot) {
    extern __shared__ float sm[];
    float* r0 = sm;                 // 16384 floats: xs+ws (phase1), w2 (phase2)
    float* xs = sm;                 // [128][64]
    float* ws = sm + 8192;          // [64][128]
    float* hs = sm + 16384;         // [128][128] hidden, later reused as output
    __shared__ float b1s[DFF], b2s[DD];
    __shared__ float rots[DD * 8];
    __shared__ float ms[ENC_PTS][8];
    int tid = threadIdx.x;
    int wid = tid >> 5, tx = tid & 31;
    int n0 = blockIdx.x * ENC_PTS;

    if (tid < DFF) b1s[tid] = b1[tid];
    else if (tid < DFF + DD) b2s[tid - DFF] = b2[tid - DFF];
    for (int t = tid; t < DD * 8; t += 512) {
        int d = t >> 3, j = t & 7;
        rots[t] = rot[d * ROTC + j];
    }

    unsigned long long acc[8][2];
    #pragma unroll
    for (int rr = 0; rr < 8; ++rr) { acc[rr][0] = 0ull; acc[rr][1] = 0ull; }

    for (int kc = 0; kc < FIN; kc += 64) {
        __syncthreads();
        for (int t = tid; t < 2048; t += 512) {
            int p = t >> 4, k4 = t & 15;
            ((float4*)xs)[p * 16 + k4] =
                ((const float4*)(inputs + (size_t)(n0 + p) * FIN + kc))[k4];
        }
        for (int t = tid; t < 2048; t += 512) {
            int k = t >> 5, c4 = t & 31;
            ((float4*)ws)[k * 32 + c4] =
                ((const float4*)(w1 + (size_t)(kc + k) * DFF))[c4];
        }
        __syncthreads();
        for (int k4 = 0; k4 < 64; k4 += 4) {
            float4 e4[8];
            #pragma unroll
            for (int rr = 0; rr < 8; ++rr)
                e4[rr] = *(const float4*)&xs[(wid * 8 + rr) * 64 + k4];
            #pragma unroll
            for (int j = 0; j < 4; ++j) {
                ulonglong2 wp = *(const ulonglong2*)&ws[(k4 + j) * DFF + tx * 4];
                #pragma unroll
                for (int rr = 0; rr < 8; ++rr) {
                    float ev = (j == 0) ? e4[rr].x : (j == 1) ? e4[rr].y
                             : (j == 2) ? e4[rr].z : e4[rr].w;
                    unsigned long long ed = dup2(ev);
                    FMA2(acc[rr][0], ed, wp.x);
                    FMA2(acc[rr][1], ed, wp.y);
                }
            }
        }
    }
    #pragma unroll
    for (int rr = 0; rr < 8; ++rr) {
        int p = wid * 8 + rr;
        float h0 = f2lo(acc[rr][0]) + b1s[tx * 4 + 0];
        float h1 = f2hi(acc[rr][0]) + b1s[tx * 4 + 1];
        float h2 = f2lo(acc[rr][1]) + b1s[tx * 4 + 2];
        float h3 = f2hi(acc[rr][1]) + b1s[tx * 4 + 3];
        h0 = h0 > 0.f ? h0 : expm1f(h0);
        h1 = h1 > 0.f ? h1 : expm1f(h1);
        h2 = h2 > 0.f ? h2 : expm1f(h2);
        h3 = h3 > 0.f ? h3 : expm1f(h3);
        *(float4*)&hs[p * DFF + tx * 4] = make_float4(h0, h1, h2, h3);
    }
    __syncthreads();

    for (int t = tid; t < 4096; t += 512)
        ((float4*)r0)[t] = ((const float4*)w2)[t];
    __syncthreads();

    #pragma unroll
    for (int rr = 0; rr < 8; ++rr) { acc[rr][0] = 0ull; acc[rr][1] = 0ull; }
    for (int k4 = 0; k4 < DFF; k4 += 4) {
        float4 e4[8];
        #pragma unroll
        for (int rr = 0; rr < 8; ++rr)
            e4[rr] = *(const float4*)&hs[(wid * 8 + rr) * DFF + k4];
        #pragma unroll
        for (int j = 0; j < 4; ++j) {
            ulonglong2 wp = *(const ulonglong2*)&r0[(k4 + j) * DD + tx * 4];
            #pragma unroll
            for (int rr = 0; rr < 8; ++rr) {
                float ev = (j == 0) ? e4[rr].x : (j == 1) ? e4[rr].y
                         : (j == 2) ? e4[rr].z : e4[rr].w;
                unsigned long long ed = dup2(ev);
                FMA2(acc[rr][0], ed, wp.x);
                FMA2(acc[rr][1], ed, wp.y);
            }
        }
    }
    __syncthreads();
    #pragma unroll
    for (int rr = 0; rr < 8; ++rr) {
        int p = wid * 8 + rr;
        int n = n0 + p;
        float o0 = f2lo(acc[rr][0]) + b2s[tx * 4 + 0];
        float o1 = f2hi(acc[rr][0]) + b2s[tx * 4 + 1];
        float o2 = f2lo(acc[rr][1]) + b2s[tx * 4 + 2];
        float o3 = f2hi(acc[rr][1]) + b2s[tx * 4 + 3];
        float4 ov = make_float4(o0, o1, o2, o3);
        *(float4*)&hs[p * DD + tx * 4] = ov;
        *(float4*)&g_pe[(size_t)n * DD + tx * 4] = ov;
        float pn = o0 * o0 + o1 * o1 + o2 * o2 + o3 * o3;
        #pragma unroll
        for (int off = 16; off; off >>= 1)
            pn += __shfl_xor_sync(0xffffffffu, pn, off);
        if (tx == 0) g_norm[n] = pn;
    }
    __syncthreads();

    for (int t = tid; t < ENC_PTS * 8; t += 512) {
        int p = t >> 3, j = t & 7;
        float m = 0.f;
        #pragma unroll 8
        for (int d = 0; d < DD; ++d) m += hs[p * DD + d] * rots[d * 8 + j];
        ms[p][j] = m;
    }
    __syncthreads();
    if (tid < ENC_PTS) {
        float best = ms[tid][0]; int bi = 0;
        #pragma unroll
        for (int j = 1; j < NBINS; ++j) {
            float v = (j < 8) ? ms[tid][j] : -ms[tid][j - 8];
            if (v > best) { best = v; bi = j; }
        }
        g_bin[n0 + tid] = bi;
    }
}

// ---------------- kernel 1b: H12 = X @ [W1a | W1b] (edge-FFN precompute) -----
__global__ __launch_bounds__(512) void h12_kernel(
        const float* __restrict__ inputs, const float* __restrict__ ew1) {
    extern __shared__ float sm[];
    float* xs = sm;                 // [128][64]
    float* ws = sm + 8192;          // [64][256]
    int tid = threadIdx.x;
    int wid = tid >> 5, tx = tid & 31;
    int n0 = blockIdx.x * 128;

    unsigned long long acc[8][4];
    #pragma unroll
    for (int rr = 0; rr < 8; ++rr)
        acc[rr][0] = acc[rr][1] = acc[rr][2] = acc[rr][3] = 0ull;

    for (int kc = 0; kc < FIN; kc += 64) {
        __syncthreads();
        for (int t = tid; t < 2048; t += 512) {
            int p = t >> 4, k4 = t & 15;
            ((float4*)xs)[p * 16 + k4] =
                ((const float4*)(inputs + (size_t)(n0 + p) * FIN + kc))[k4];
        }
        for (int t = tid; t < 4096; t += 512) {
            int k = t >> 6, j4 = t & 63;
            const float* srcp = (j4 < 32)
                ? (ew1 + (size_t)(kc + k) * DFF + j4 * 4)
                : (ew1 + (size_t)(256 + kc + k) * DFF + (j4 - 32) * 4);
            ((float4*)ws)[k * 64 + j4] = *(const float4*)srcp;
        }
        __syncthreads();
        for (int k4 = 0; k4 < 64; k4 += 4) {
            float4 e4[8];
            #pragma unroll
            for (int rr = 0; rr < 8; ++rr)
                e4[rr] = *(const float4*)&xs[(wid * 8 + rr) * 64 + k4];
            #pragma unroll
            for (int j = 0; j < 4; ++j) {
                ulonglong2 wa = *(const ulonglong2*)&ws[(k4 + j) * 256 + tx * 4];
                ulonglong2 wb = *(const ulonglong2*)&ws[(k4 + j) * 256 + 128 + tx * 4];
                #pragma unroll
                for (int rr = 0; rr < 8; ++rr) {
                    float ev = (j == 0) ? e4[rr].x : (j == 1) ? e4[rr].y
                             : (j == 2) ? e4[rr].z : e4[rr].w;
                    unsigned long long ed = dup2(ev);
                    FMA2(acc[rr][0], ed, wa.x);
                    FMA2(acc[rr][1], ed, wa.y);
                    FMA2(acc[rr][2], ed, wb.x);
                    FMA2(acc[rr][3], ed, wb.y);
                }
            }
        }
    }
    #pragma unroll
    for (int rr = 0; rr < 8; ++rr) {
        size_t n = (size_t)(n0 + wid * 8 + rr);
        *(float4*)&g_h12[n * 256 + tx * 4] =
            make_float4(f2lo(acc[rr][0]), f2hi(acc[rr][0]),
                        f2lo(acc[rr][1]), f2hi(acc[rr][1]));
        *(float4*)&g_h12[n * 256 + 128 + tx * 4] =
            make_float4(f2lo(acc[rr][2]), f2hi(acc[rr][2]),
                        f2lo(acc[rr][3]), f2hi(acc[rr][3]));
    }
}

// ---------------- kernel 2: stable counting sort (match_any) + bins out ------
__global__ __launch_bounds__(256) void sort_kernel(float* __restrict__ out,
                                                   int out_size) {
    int b = blockIdx.x;
    __shared__ int bins[N_];
    __shared__ int cnt[NBINS];
    __shared__ int basebin[NBINS];
    __shared__ int wcnt[8][NBINS];
    int tid = threadIdx.x, wid = tid >> 5, lane = tid & 31;
    unsigned ltmask = (1u << lane) - 1u;
    for (int i = tid; i < N_; i += 256) bins[i] = g_bin[b*N_ + i];
    if (tid < NBINS) cnt[tid] = 0;
    __syncthreads();
    for (int i = tid; i < N_; i += 256) {
        int bi = bins[i];
        unsigned m = __match_any_sync(0xffffffffu, bi);
        if ((m & ltmask) == 0) atomicAdd(&cnt[bi], __popc(m));
    }
    __syncthreads();
    if (tid == 0) {
        int s = 0;
        for (int k = 0; k < NBINS; ++k) { basebin[k] = s; s += cnt[k]; }
    }
    __syncthreads();
    for (int c0 = 0; c0 < N_; c0 += 256) {
        int i = c0 + tid;
        int bi = (i < N_) ? bins[i] : -1;
        unsigned m = __match_any_sync(0xffffffffu, bi);
        int wrank = __popc(m & ltmask);
        if (tid < 128) wcnt[tid >> 4][tid & 15] = 0;
        __syncthreads();
        if ((m & ltmask) == 0 && bi >= 0) wcnt[wid][bi] = __popc(m);
        __syncthreads();
        if (bi >= 0) {
            int off = basebin[bi];
            #pragma unroll
            for (int w = 0; w < 8; ++w) if (w < wid) off += wcnt[w][bi];
            g_perm[b*N_ + off + wrank] = i;
        }
        __syncthreads();
        if (tid < NBINS) {
            int t = 0;
            #pragma unroll
            for (int w = 0; w < 8; ++w) t += wcnt[w][tid];
            basebin[tid] += t;
        }
        __syncthreads();
    }
    for (int i = tid; i < N_; i += 256) {
        int idx = 4*E_TOT + b*N_ + i;
        if (idx < out_size) out[idx] = (float)g_perm[b*N_ + i];
    }
}

// ---------------- kernel 3: top-8 by min d2, 4 rows per 4-lane group ---------
// 128 blocks = 64 (b,bin) x 2 row slabs of 256. Each column quarter loaded
// from smem feeds 4 rows (4x less LDS traffic). Top-k state = u64 keys in smem
// (d2 bits << 32 | idx): unsigned ascending == (d2 asc, idx asc) tie-break.
#define TK_COLS 64
__global__ __launch_bounds__(256) void topk_kernel() {
    int bb = blockIdx.x;
    int rg = bb & 1;
    int bbin = bb >> 1;
    int b = bbin / NBINS, bin = bbin % NBINS;
    extern __shared__ float smx[];
    float4* colbuf = (float4*)smx;                       // 64 cols x 32 f4 = 32KB
    float* cnorm = smx + TK_COLS * 128;                  // [64]
    unsigned long long* keys =
        (unsigned long long*)(smx + TK_COLS * 128 + TK_COLS);  // [256][8] = 16KB
    const int* perm = g_perm + b*N_ + bin*BINSZ;
    const float* pe = g_pe + (size_t)b*N_*DD;
    int tid = threadIdx.x;
    int grp = tid >> 2, l4 = tid & 3;                    // 64 groups x 4 lanes
    int rbase = rg * 256;

    bool rv[4]; int rsrc[4]; float rn[4];
    ulonglong2 rp[4][8];
    #pragma unroll
    for (int r = 0; r < 4; ++r) {
        int row = rbase + grp + 64*r;
        rv[r] = row < BINSZ;
        int rowc = rv[r] ? row : 0;
        rsrc[r] = perm[rowc];
        rn[r] = g_norm[b*N_ + rsrc[r]];
        const ulonglong2* prow = (const ulonglong2*)(pe + (size_t)rsrc[r]*DD) + l4*8;
        #pragma unroll
        for (int kk = 0; kk < 8; ++kk) rp[r][kk] = prow[kk];
    }
    for (int t = tid; t < 256*8; t += 256) keys[t] = ~0ull;

    for (int cc = 0; cc < BINSZ; cc += TK_COLS) {
        int csize = min(TK_COLS, BINSZ - cc);            // 64 or 52 (even)
        __syncthreads();
        for (int t = tid; t < csize*32; t += 256) {
            int c = t >> 5, k = t & 31;
            colbuf[c*32 + k] = ((const float4*)(pe + (size_t)perm[cc + c]*DD))[k];
        }
        for (int t = tid; t < csize; t += 256)
            cnorm[t] = g_norm[b*N_ + perm[cc + t]];
        __syncthreads();
        for (int c = 0; c < csize; c += 2) {
            unsigned long long a[4][2], e[4][2];
            #pragma unroll
            for (int r = 0; r < 4; ++r) {
                a[r][0] = a[r][1] = 0ull;
                e[r][0] = e[r][1] = 0ull;
            }
            const ulonglong2* col0 = (const ulonglong2*)&colbuf[c*32 + l4*8];
            const ulonglong2* col1 = (const ulonglong2*)&colbuf[(c+1)*32 + l4*8];
            #pragma unroll
            for (int kk = 0; kk < 8; ++kk) {
                int ke = (kk + 2*l4) & 7;                // bank stagger
                ulonglong2 c0 = col0[ke];
                ulonglong2 c1 = col1[ke];
                #pragma unroll
                for (int r = 0; r < 4; ++r) {
                    FMA2(a[r][0], rp[r][ke].x, c0.x);
                    FMA2(a[r][1], rp[r][ke].y, c0.y);
                    FMA2(e[r][0], rp[r][ke].x, c1.x);
                    FMA2(e[r][1], rp[r][ke].y, c1.y);
                }
            }
            #pragma unroll
            for (int r = 0; r < 4; ++r) {
                float p0 = (f2lo(a[r][0]) + f2hi(a[r][0]))
                         + (f2lo(a[r][1]) + f2hi(a[r][1]));
                float p1 = (f2lo(e[r][0]) + f2hi(e[r][0]))
                         + (f2lo(e[r][1]) + f2hi(e[r][1]));
                p0 += __shfl_down_sync(0xffffffffu, p0, 2, 4);
                p0 += __shfl_down_sync(0xffffffffu, p0, 1, 4);
                p1 += __shfl_down_sync(0xffffffffu, p1, 2, 4);
                p1 += __shfl_down_sync(0xffffffffu, p1, 1, 4);
                if (l4 == 0 && rv[r]) {
                    unsigned long long* kr = &keys[((r << 6) | grp) * 8];
                    float d20 = fmaxf((rn[r] - 2.0f*p0) + cnorm[c], 1e-6f);
                    unsigned long long k0 =
                        ((unsigned long long)__float_as_uint(d20) << 32)
                        | (unsigned)(cc + c);
                    if (k0 < kr[7]) {
                        kr[7] = k0;
                        #pragma unroll
                        for (int s = 7; s > 0; --s) {
                            if (kr[s] < kr[s-1]) {
                                unsigned long long tmp = kr[s];
                                kr[s] = kr[s-1]; kr[s-1] = tmp;
                            } else break;
                        }
                    }
                    float d21 = fmaxf((rn[r] - 2.0f*p1) + cnorm[c+1], 1e-6f);
                    unsigned long long k1 =
                        ((unsigned long long)__float_as_uint(d21) << 32)
                        | (unsigned)(cc + c + 1);
                    if (k1 < kr[7]) {
                        kr[7] = k1;
                        #pragma unroll
                        for (int s = 7; s > 0; --s) {
                            if (kr[s] < kr[s-1]) {
                                unsigned long long tmp = kr[s];
                                kr[s] = kr[s-1]; kr[s-1] = tmp;
                            } else break;
                        }
                    }
                }
            }
        }
    }
    __syncthreads();
    if (l4 == 0) {
        #pragma unroll
        for (int r = 0; r < 4; ++r) {
            if (!rv[r]) continue;
            unsigned long long* kr = &keys[((r << 6) | grp) * 8];
            int dsts[KNN]; float vals[KNN];
            #pragma unroll
            for (int s = 0; s < KNN; ++s) {
                unsigned long long k = kr[s];
                float d2 = __uint_as_float((unsigned)(k >> 32));
                dsts[s] = perm[(unsigned)k];
                vals[s] = expf(-0.1f * sqrtf(d2));
            }
            #pragma unroll
            for (int i = 1; i < KNN; ++i) {
                int dk = dsts[i]; float vk = vals[i]; int j = i - 1;
                while (j >= 0 && dsts[j] > dk) {
                    dsts[j+1] = dsts[j]; vals[j+1] = vals[j]; --j;
                }
                dsts[j+1] = dk; vals[j+1] = vk;
            }
            size_t base = ((size_t)b*N_ + rsrc[r]) * KNN;
            #pragma unroll
            for (int s = 0; s < KNN; ++s) {
                g_dst[base+s] = dsts[s]; g_val[base+s] = vals[s];
            }
        }
    }
}

// ---------------- kernel 4: edge epilogue (gather H1/H2 + elu + dot + sig) ---
__global__ __launch_bounds__(256) void edge_kernel(
        const float* __restrict__ ew1, const float* __restrict__ b1,
        const float* __restrict__ w2, const float* __restrict__ b2v,
        float* __restrict__ out, int out_size) {
    int wid = threadIdx.x >> 5, lane = threadIdx.x & 31;
    int p = blockIdx.x * 8 + wid;           // 0..31999
    int b = p / N_;
    int src = p % N_;
    float4 w1c = *(const float4*)&ew1[(size_t)512 * DFF + lane * 4];
    float4 b14 = *(const float4*)&b1[lane * 4];
    float4 w24 = *(const float4*)&w2[lane * 4];
    float b2s = b2v[0];
    float4 h1 = *(const float4*)&g_h12[(size_t)p * 256 + lane * 4];
    float bx = h1.x + b14.x, by = h1.y + b14.y;
    float bz = h1.z + b14.z, bw = h1.w + b14.w;
    size_t ebase = (size_t)p * KNN;
    #pragma unroll
    for (int i = 0; i < KNN; ++i) {
        int dst = g_dst[ebase + i];
        float val = g_val[ebase + i];
        float4 h2 = *(const float4*)&g_h12[((size_t)(b*N_ + dst)) * 256 + 128 + lane * 4];
        float x0 = bx + h2.x + val * w1c.x;
        float x1 = by + h2.y + val * w1c.y;
        float x2 = bz + h2.z + val * w1c.z;
        float x3 = bw + h2.w + val * w1c.w;
        x0 = x0 > 0.f ? x0 : expm1f(x0);
        x1 = x1 > 0.f ? x1 : expm1f(x1);
        x2 = x2 > 0.f ? x2 : expm1f(x2);
        x3 = x3 > 0.f ? x3 : expm1f(x3);
        float s = x0 * w24.x + x1 * w24.y + x2 * w24.z + x3 * w24.w;
        #pragma unroll
        for (int off = 16; off; off >>= 1) s += __shfl_down_sync(0xffffffffu, s, off);
        if (lane == 0) {
            int eid = (int)ebase + i;
            if (3*E_TOT + eid < out_size)
                out[3*E_TOT + eid] = 1.f / (1.f + expf(-(s + b2s)));
            if (eid*3 + 2 < out_size) {
                out[eid*3 + 0] = (float)b;
                out[eid*3 + 1] = (float)src;
                out[eid*3 + 2] = (float)dst;
            }
        }
    }
}

// -----------------------------------------------------------------------------
extern "C" void kernel_launch(void* const* d_in, const int* in_sizes, int n_in,
                              void* d_out, int out_size) {
    const float* inputs  = (const float*)d_in[0];
    const float* enc_w1  = (const float*)d_in[1];
    const float* enc_b1  = (const float*)d_in[2];
    const float* enc_w2  = (const float*)d_in[3];
    const float* enc_b2  = (const float*)d_in[4];
    const float* edge_w1 = (const float*)d_in[5];
    const float* edge_b1 = (const float*)d_in[6];
    const float* edge_w2 = (const float*)d_in[7];
    const float* edge_b2 = (const float*)d_in[8];
    const float* rot     = (const float*)d_in[9];
    float* out = (float*)d_out;

    size_t enc_smem = (size_t)(16384 + 16384) * sizeof(float);   // 128 KB
    cudaFuncSetAttribute(enc_kernel, cudaFuncAttributeMaxDynamicSharedMemorySize,
                         (int)enc_smem);
    enc_kernel<<<(B_*N_)/ENC_PTS, 512, enc_smem>>>(inputs, enc_w1, enc_b1,
                                                   enc_w2, enc_b2, rot);

    size_t h12_smem = (size_t)(8192 + 16384) * sizeof(float);    // 96 KB
    cudaFuncSetAttribute(h12_kernel, cudaFuncAttributeMaxDynamicSharedMemorySize,
                         (int)h12_smem);
    h12_kernel<<<(B_*N_)/128, 512, h12_smem>>>(inputs, edge_w1);

    sort_kernel<<<B_, 256>>>(out, out_size);

    size_t tk_smem = (size_t)(TK_COLS * 128 + TK_COLS) * sizeof(float)
                   + 256 * 8 * sizeof(unsigned long long);       // ~48.3 KB
    cudaFuncSetAttribute(topk_kernel, cudaFuncAttributeMaxDynamicSharedMemorySize,
                         (int)tk_smem);
    topk_kernel<<<B_*NBINS*2, 256, tk_smem>>>();

    edge_kernel<<<(B_*N_)/8, 256>>>(edge_w1, edge_b1, edge_w2, edge_b2,
                                    out, out_size);
}

// round 6
// speedup vs baseline: 5.3227x; 1.1411x over previous
#include <cuda_runtime.h>
#include <math.h>

#define B_    4
#define N_    8000
#define FIN   256
#define DD    128
#define DFF   128
#define NBINS 16
#define BINSZ 500
#define KNN   8
#define E_TOT (B_*N_*KNN)     /* 256000 */
#define ROTC  100             /* MAX_NUM_BINS/2, row stride of rot */

// ---------------- scratch (static device globals; no allocation) -------------
__device__ float g_pe[B_*N_*DD];          // encoded points
__device__ float g_norm[B_*N_];           // squared norms of encoded points
__device__ int   g_bin[B_*N_];            // LSH bin per point
__device__ int   g_perm[B_*N_];           // stable argsort by bin == bins_split
__device__ int   g_dst[E_TOT];            // per (b,src,slot) dst, dst-sorted
__device__ float g_val[E_TOT];            // matching kernel values
__device__ float g_h12[(size_t)B_*N_*256];// [point][0:128]=X*W1a, [128:256]=X*W1b

// ---------------- packed f32x2 helpers ---------------------------------------
#define FMA2(d, a, b) asm("fma.rn.f32x2 %0, %1, %2, %0;" : "+l"(d) : "l"(a), "l"(b))

__device__ __forceinline__ unsigned long long dup2(float v) {
    unsigned iv = __float_as_uint(v);
    unsigned long long r;
    asm("mov.b64 %0, {%1, %1};" : "=l"(r) : "r"(iv), "r"(iv));
    return r;
}
__device__ __forceinline__ float f2lo(unsigned long long u) {
    return __uint_as_float((unsigned)u);
}
__device__ __forceinline__ float f2hi(unsigned long long u) {
    return __uint_as_float((unsigned)(u >> 32));
}

// ---------------- cp.async helpers --------------------------------------------
#define CPA16(dst, src) asm volatile( \
    "cp.async.ca.shared.global [%0], [%1], 16;" :: "r"(dst), "l"(src))
#define CPA4(dst, src) asm volatile( \
    "cp.async.ca.shared.global [%0], [%1], 4;" :: "r"(dst), "l"(src))
#define CPACOMMIT() asm volatile("cp.async.commit_group;")
#define CPAWAIT0()  asm volatile("cp.async.wait_group 0;")

// ---------------- kernel 1: tiled encoder FFN + norms + LSH bin --------------
#define ENC_PTS 128
__global__ __launch_bounds__(512) void enc_kernel(
        const float* __restrict__ inputs,
        const float* __restrict__ w1, const float* __restrict__ b1,
        const float* __restrict__ w2, const float* __restrict__ b2,
        const float* __restrict__ rot) {
    extern __shared__ float sm[];
    float* r0 = sm;                 // 16384 floats: xs+ws (phase1), w2 (phase2)
    float* xs = sm;                 // [128][64]
    float* ws = sm + 8192;          // [64][128]
    float* hs = sm + 16384;         // [128][128] hidden, later reused as output
    __shared__ float b1s[DFF], b2s[DD];
    __shared__ float rots[DD * 8];
    __shared__ float ms[ENC_PTS][8];
    int tid = threadIdx.x;
    int wid = tid >> 5, tx = tid & 31;
    int n0 = blockIdx.x * ENC_PTS;

    if (tid < DFF) b1s[tid] = b1[tid];
    else if (tid < DFF + DD) b2s[tid - DFF] = b2[tid - DFF];
    for (int t = tid; t < DD * 8; t += 512) {
        int d = t >> 3, j = t & 7;
        rots[t] = rot[d * ROTC + j];
    }

    unsigned long long acc[8][2];
    #pragma unroll
    for (int rr = 0; rr < 8; ++rr) { acc[rr][0] = 0ull; acc[rr][1] = 0ull; }

    for (int kc = 0; kc < FIN; kc += 64) {
        __syncthreads();
        for (int t = tid; t < 2048; t += 512) {
            int p = t >> 4, k4 = t & 15;
            ((float4*)xs)[p * 16 + k4] =
                ((const float4*)(inputs + (size_t)(n0 + p) * FIN + kc))[k4];
        }
        for (int t = tid; t < 2048; t += 512) {
            int k = t >> 5, c4 = t & 31;
            ((float4*)ws)[k * 32 + c4] =
                ((const float4*)(w1 + (size_t)(kc + k) * DFF))[c4];
        }
        __syncthreads();
        for (int k4 = 0; k4 < 64; k4 += 4) {
            float4 e4[8];
            #pragma unroll
            for (int rr = 0; rr < 8; ++rr)
                e4[rr] = *(const float4*)&xs[(wid * 8 + rr) * 64 + k4];
            #pragma unroll
            for (int j = 0; j < 4; ++j) {
                ulonglong2 wp = *(const ulonglong2*)&ws[(k4 + j) * DFF + tx * 4];
                #pragma unroll
                for (int rr = 0; rr < 8; ++rr) {
                    float ev = (j == 0) ? e4[rr].x : (j == 1) ? e4[rr].y
                             : (j == 2) ? e4[rr].z : e4[rr].w;
                    unsigned long long ed = dup2(ev);
                    FMA2(acc[rr][0], ed, wp.x);
                    FMA2(acc[rr][1], ed, wp.y);
                }
            }
        }
    }
    #pragma unroll
    for (int rr = 0; rr < 8; ++rr) {
        int p = wid * 8 + rr;
        float h0 = f2lo(acc[rr][0]) + b1s[tx * 4 + 0];
        float h1 = f2hi(acc[rr][0]) + b1s[tx * 4 + 1];
        float h2 = f2lo(acc[rr][1]) + b1s[tx * 4 + 2];
        float h3 = f2hi(acc[rr][1]) + b1s[tx * 4 + 3];
        h0 = h0 > 0.f ? h0 : expm1f(h0);
        h1 = h1 > 0.f ? h1 : expm1f(h1);
        h2 = h2 > 0.f ? h2 : expm1f(h2);
        h3 = h3 > 0.f ? h3 : expm1f(h3);
        *(float4*)&hs[p * DFF + tx * 4] = make_float4(h0, h1, h2, h3);
    }
    __syncthreads();

    for (int t = tid; t < 4096; t += 512)
        ((float4*)r0)[t] = ((const float4*)w2)[t];
    __syncthreads();

    #pragma unroll
    for (int rr = 0; rr < 8; ++rr) { acc[rr][0] = 0ull; acc[rr][1] = 0ull; }
    for (int k4 = 0; k4 < DFF; k4 += 4) {
        float4 e4[8];
        #pragma unroll
        for (int rr = 0; rr < 8; ++rr)
            e4[rr] = *(const float4*)&hs[(wid * 8 + rr) * DFF + k4];
        #pragma unroll
        for (int j = 0; j < 4; ++j) {
            ulonglong2 wp = *(const ulonglong2*)&r0[(k4 + j) * DD + tx * 4];
            #pragma unroll
            for (int rr = 0; rr < 8; ++rr) {
                float ev = (j == 0) ? e4[rr].x : (j == 1) ? e4[rr].y
                         : (j == 2) ? e4[rr].z : e4[rr].w;
                unsigned long long ed = dup2(ev);
                FMA2(acc[rr][0], ed, wp.x);
                FMA2(acc[rr][1], ed, wp.y);
            }
        }
    }
    __syncthreads();
    #pragma unroll
    for (int rr = 0; rr < 8; ++rr) {
        int p = wid * 8 + rr;
        int n = n0 + p;
        float o0 = f2lo(acc[rr][0]) + b2s[tx * 4 + 0];
        float o1 = f2hi(acc[rr][0]) + b2s[tx * 4 + 1];
        float o2 = f2lo(acc[rr][1]) + b2s[tx * 4 + 2];
        float o3 = f2hi(acc[rr][1]) + b2s[tx * 4 + 3];
        float4 ov = make_float4(o0, o1, o2, o3);
        *(float4*)&hs[p * DD + tx * 4] = ov;
        *(float4*)&g_pe[(size_t)n * DD + tx * 4] = ov;
        float pn = o0 * o0 + o1 * o1 + o2 * o2 + o3 * o3;
        #pragma unroll
        for (int off = 16; off; off >>= 1)
            pn += __shfl_xor_sync(0xffffffffu, pn, off);
        if (tx == 0) g_norm[n] = pn;
    }
    __syncthreads();

    for (int t = tid; t < ENC_PTS * 8; t += 512) {
        int p = t >> 3, j = t & 7;
        float m = 0.f;
        #pragma unroll 8
        for (int d = 0; d < DD; ++d) m += hs[p * DD + d] * rots[d * 8 + j];
        ms[p][j] = m;
    }
    __syncthreads();
    if (tid < ENC_PTS) {
        float best = ms[tid][0]; int bi = 0;
        #pragma unroll
        for (int j = 1; j < NBINS; ++j) {
            float v = (j < 8) ? ms[tid][j] : -ms[tid][j - 8];
            if (v > best) { best = v; bi = j; }
        }
        g_bin[n0 + tid] = bi;
    }
}

// ---------------- kernel 1b: H12 = X @ [W1a | W1b] (edge-FFN precompute) -----
__global__ __launch_bounds__(512) void h12_kernel(
        const float* __restrict__ inputs, const float* __restrict__ ew1) {
    extern __shared__ float sm[];
    float* xs = sm;                 // [128][64]
    float* ws = sm + 8192;          // [64][256]
    int tid = threadIdx.x;
    int wid = tid >> 5, tx = tid & 31;
    int n0 = blockIdx.x * 128;

    unsigned long long acc[8][4];
    #pragma unroll
    for (int rr = 0; rr < 8; ++rr)
        acc[rr][0] = acc[rr][1] = acc[rr][2] = acc[rr][3] = 0ull;

    for (int kc = 0; kc < FIN; kc += 64) {
        __syncthreads();
        for (int t = tid; t < 2048; t += 512) {
            int p = t >> 4, k4 = t & 15;
            ((float4*)xs)[p * 16 + k4] =
                ((const float4*)(inputs + (size_t)(n0 + p) * FIN + kc))[k4];
        }
        for (int t = tid; t < 4096; t += 512) {
            int k = t >> 6, j4 = t & 63;
            const float* srcp = (j4 < 32)
                ? (ew1 + (size_t)(kc + k) * DFF + j4 * 4)
                : (ew1 + (size_t)(256 + kc + k) * DFF + (j4 - 32) * 4);
            ((float4*)ws)[k * 64 + j4] = *(const float4*)srcp;
        }
        __syncthreads();
        for (int k4 = 0; k4 < 64; k4 += 4) {
            float4 e4[8];
            #pragma unroll
            for (int rr = 0; rr < 8; ++rr)
                e4[rr] = *(const float4*)&xs[(wid * 8 + rr) * 64 + k4];
            #pragma unroll
            for (int j = 0; j < 4; ++j) {
                ulonglong2 wa = *(const ulonglong2*)&ws[(k4 + j) * 256 + tx * 4];
                ulonglong2 wb = *(const ulonglong2*)&ws[(k4 + j) * 256 + 128 + tx * 4];
                #pragma unroll
                for (int rr = 0; rr < 8; ++rr) {
                    float ev = (j == 0) ? e4[rr].x : (j == 1) ? e4[rr].y
                             : (j == 2) ? e4[rr].z : e4[rr].w;
                    unsigned long long ed = dup2(ev);
                    FMA2(acc[rr][0], ed, wa.x);
                    FMA2(acc[rr][1], ed, wa.y);
                    FMA2(acc[rr][2], ed, wb.x);
                    FMA2(acc[rr][3], ed, wb.y);
                }
            }
        }
    }
    #pragma unroll
    for (int rr = 0; rr < 8; ++rr) {
        size_t n = (size_t)(n0 + wid * 8 + rr);
        *(float4*)&g_h12[n * 256 + tx * 4] =
            make_float4(f2lo(acc[rr][0]), f2hi(acc[rr][0]),
                        f2lo(acc[rr][1]), f2hi(acc[rr][1]));
        *(float4*)&g_h12[n * 256 + 128 + tx * 4] =
            make_float4(f2lo(acc[rr][2]), f2hi(acc[rr][2]),
                        f2lo(acc[rr][3]), f2hi(acc[rr][3]));
    }
}

// ---------------- kernel 2: stable counting sort (match_any) + bins out ------
__global__ __launch_bounds__(256) void sort_kernel(float* __restrict__ out,
                                                   int out_size) {
    int b = blockIdx.x;
    __shared__ int bins[N_];
    __shared__ int cnt[NBINS];
    __shared__ int basebin[NBINS];
    __shared__ int wcnt[8][NBINS];
    int tid = threadIdx.x, wid = tid >> 5, lane = tid & 31;
    unsigned ltmask = (1u << lane) - 1u;
    for (int i = tid; i < N_; i += 256) bins[i] = g_bin[b*N_ + i];
    if (tid < NBINS) cnt[tid] = 0;
    __syncthreads();
    for (int i = tid; i < N_; i += 256) {
        int bi = bins[i];
        unsigned m = __match_any_sync(0xffffffffu, bi);
        if ((m & ltmask) == 0) atomicAdd(&cnt[bi], __popc(m));
    }
    __syncthreads();
    if (tid == 0) {
        int s = 0;
        for (int k = 0; k < NBINS; ++k) { basebin[k] = s; s += cnt[k]; }
    }
    __syncthreads();
    for (int c0 = 0; c0 < N_; c0 += 256) {
        int i = c0 + tid;
        int bi = (i < N_) ? bins[i] : -1;
        unsigned m = __match_any_sync(0xffffffffu, bi);
        int wrank = __popc(m & ltmask);
        if (tid < 128) wcnt[tid >> 4][tid & 15] = 0;
        __syncthreads();
        if ((m & ltmask) == 0 && bi >= 0) wcnt[wid][bi] = __popc(m);
        __syncthreads();
        if (bi >= 0) {
            int off = basebin[bi];
            #pragma unroll
            for (int w = 0; w < 8; ++w) if (w < wid) off += wcnt[w][bi];
            g_perm[b*N_ + off + wrank] = i;
        }
        __syncthreads();
        if (tid < NBINS) {
            int t = 0;
            #pragma unroll
            for (int w = 0; w < 8; ++w) t += wcnt[w][tid];
            basebin[tid] += t;
        }
        __syncthreads();
    }
    for (int i = tid; i < N_; i += 256) {
        int idx = 4*E_TOT + b*N_ + i;
        if (idx < out_size) out[idx] = (float)g_perm[b*N_ + i];
    }
}

// ---------------- kernel 3: top-8 by min d2 -----------------------------------
// 256 blocks = 64 (b,bin) x 4 row slabs of 128. 2 rows per 4-lane group (regs),
// double-buffered 32-col tiles via cp.async. Top-k keys (d2<<32|idx) in smem.
#define TKC 32
__global__ __launch_bounds__(256, 2) void topk_kernel() {
    int bb = blockIdx.x;
    int rg = bb & 3;
    int bbin = bb >> 2;
    int b = bbin / NBINS, bin = bbin % NBINS;
    extern __shared__ float smx[];
    float4* colbuf4 = (float4*)smx;                        // [2][32][32] f4 32KB
    float* cns = smx + 2 * TKC * 128;                      // [2][32]
    unsigned long long* keys =
        (unsigned long long*)(smx + 2 * TKC * 128 + 2 * TKC);  // [128][8] 8KB
    unsigned smem_u = (unsigned)__cvta_generic_to_shared(smx);
    unsigned cb_u   = smem_u;                              // colbuf bytes
    unsigned cn_u   = smem_u + 2 * TKC * 128 * 4;          // cnorm bytes

    const int* perm = g_perm + b*N_ + bin*BINSZ;
    const float* pe = g_pe + (size_t)b*N_*DD;
    const float* nrm = g_norm + b*N_;
    int tid = threadIdx.x;
    int grp = tid >> 2, l4 = tid & 3;                      // 64 groups x 4 lanes
    int rbase = rg * 128;

    bool rv[2]; int rsrc[2]; float rn[2];
    ulonglong2 rp[2][8];
    #pragma unroll
    for (int r = 0; r < 2; ++r) {
        int row = rbase + grp + 64*r;
        rv[r] = row < BINSZ;
        int rowc = rv[r] ? row : 0;
        rsrc[r] = perm[rowc];
        rn[r] = nrm[rsrc[r]];
        const ulonglong2* prow = (const ulonglong2*)(pe + (size_t)rsrc[r]*DD) + l4*8;
        #pragma unroll
        for (int kk = 0; kk < 8; ++kk) rp[r][kk] = prow[kk];
    }
    for (int t = tid; t < 128*8; t += 256) keys[t] = ~0ull;

    const int NT = (BINSZ + TKC - 1) / TKC;                // 16 tiles
    // prefetch tile 0 into buffer 0
    {
        int csize = TKC;
        for (int t = tid; t < csize*32; t += 256) {
            int c = t >> 5, k = t & 31;
            CPA16(cb_u + (unsigned)t * 16,
                  (const void*)(pe + (size_t)perm[c]*DD + k*4));
        }
        if (tid < csize) CPA4(cn_u + tid*4, (const void*)(nrm + perm[tid]));
        CPACOMMIT();
    }
    CPAWAIT0();
    __syncthreads();

    for (int tIdx = 0; tIdx < NT; ++tIdx) {
        int bf = tIdx & 1;
        int cc = tIdx * TKC;
        int csize = min(TKC, BINSZ - cc);                  // 32 or 20 (even)
        // issue prefetch of next tile into other buffer
        if (tIdx + 1 < NT) {
            int ncc = cc + TKC;
            int ncs = min(TKC, BINSZ - ncc);
            unsigned cbn = cb_u + (unsigned)(bf ^ 1) * TKC * 128 * 4;
            for (int t = tid; t < ncs*32; t += 256) {
                int c = t >> 5, k = t & 31;
                CPA16(cbn + (unsigned)t * 16,
                      (const void*)(pe + (size_t)perm[ncc + c]*DD + k*4));
            }
            if (tid < ncs) CPA4(cn_u + ((bf ^ 1) * TKC + tid) * 4,
                                (const void*)(nrm + perm[ncc + tid]));
            CPACOMMIT();
        }
        const float4* cb = colbuf4 + bf * TKC * 32;
        const float* cnorm = cns + bf * TKC;
        for (int c = 0; c < csize; c += 2) {
            unsigned long long a[2][2], e[2][2];
            a[0][0]=a[0][1]=a[1][0]=a[1][1]=0ull;
            e[0][0]=e[0][1]=e[1][0]=e[1][1]=0ull;
            const ulonglong2* col0 = (const ulonglong2*)&cb[c*32 + l4*8];
            const ulonglong2* col1 = (const ulonglong2*)&cb[(c+1)*32 + l4*8];
            #pragma unroll
            for (int kk = 0; kk < 8; ++kk) {
                int ke = (kk + 2*l4) & 7;                  // bank stagger
                ulonglong2 c0 = col0[ke];
                ulonglong2 c1 = col1[ke];
                #pragma unroll
                for (int r = 0; r < 2; ++r) {
                    FMA2(a[r][0], rp[r][ke].x, c0.x);
                    FMA2(a[r][1], rp[r][ke].y, c0.y);
                    FMA2(e[r][0], rp[r][ke].x, c1.x);
                    FMA2(e[r][1], rp[r][ke].y, c1.y);
                }
            }
            #pragma unroll
            for (int r = 0; r < 2; ++r) {
                float p0 = (f2lo(a[r][0]) + f2hi(a[r][0]))
                         + (f2lo(a[r][1]) + f2hi(a[r][1]));
                float p1 = (f2lo(e[r][0]) + f2hi(e[r][0]))
                         + (f2lo(e[r][1]) + f2hi(e[r][1]));
                p0 += __shfl_down_sync(0xffffffffu, p0, 2, 4);
                p0 += __shfl_down_sync(0xffffffffu, p0, 1, 4);
                p1 += __shfl_down_sync(0xffffffffu, p1, 2, 4);
                p1 += __shfl_down_sync(0xffffffffu, p1, 1, 4);
                if (l4 == 0 && rv[r]) {
                    unsigned long long* kr = &keys[((r << 6) | grp) * 8];
                    float d20 = fmaxf((rn[r] - 2.0f*p0) + cnorm[c], 1e-6f);
                    unsigned long long k0 =
                        ((unsigned long long)__float_as_uint(d20) << 32)
                        | (unsigned)(cc + c);
                    if (k0 < kr[7]) {
                        kr[7] = k0;
                        #pragma unroll
                        for (int s = 7; s > 0; --s) {
                            if (kr[s] < kr[s-1]) {
                                unsigned long long tmp = kr[s];
                                kr[s] = kr[s-1]; kr[s-1] = tmp;
                            } else break;
                        }
                    }
                    float d21 = fmaxf((rn[r] - 2.0f*p1) + cnorm[c+1], 1e-6f);
                    unsigned long long k1 =
                        ((unsigned long long)__float_as_uint(d21) << 32)
                        | (unsigned)(cc + c + 1);
                    if (k1 < kr[7]) {
                        kr[7] = k1;
                        #pragma unroll
                        for (int s = 7; s > 0; --s) {
                            if (kr[s] < kr[s-1]) {
                                unsigned long long tmp = kr[s];
                                kr[s] = kr[s-1]; kr[s-1] = tmp;
                            } else break;
                        }
                    }
                }
            }
        }
        CPAWAIT0();
        __syncthreads();
    }
    if (l4 == 0) {
        #pragma unroll
        for (int r = 0; r < 2; ++r) {
            if (!rv[r]) continue;
            unsigned long long* kr = &keys[((r << 6) | grp) * 8];
            int dsts[KNN]; float vals[KNN];
            #pragma unroll
            for (int s = 0; s < KNN; ++s) {
                unsigned long long k = kr[s];
                float d2 = __uint_as_float((unsigned)(k >> 32));
                dsts[s] = perm[(unsigned)k];
                vals[s] = expf(-0.1f * sqrtf(d2));
            }
            #pragma unroll
            for (int i = 1; i < KNN; ++i) {
                int dk = dsts[i]; float vk = vals[i]; int j = i - 1;
                while (j >= 0 && dsts[j] > dk) {
                    dsts[j+1] = dsts[j]; vals[j+1] = vals[j]; --j;
                }
                dsts[j+1] = dk; vals[j+1] = vk;
            }
            size_t base = ((size_t)b*N_ + rsrc[r]) * KNN;
            #pragma unroll
            for (int s = 0; s < KNN; ++s) {
                g_dst[base+s] = dsts[s]; g_val[base+s] = vals[s];
            }
        }
    }
}

// ---------------- kernel 4: edge epilogue (gather H1/H2 + elu + dot + sig) ---
__global__ __launch_bounds__(256) void edge_kernel(
        const float* __restrict__ ew1, const float* __restrict__ b1,
        const float* __restrict__ w2, const float* __restrict__ b2v,
        float* __restrict__ out, int out_size) {
    int wid = threadIdx.x >> 5, lane = threadIdx.x & 31;
    int p = blockIdx.x * 8 + wid;           // 0..31999
    int b = p / N_;
    int src = p % N_;
    float4 w1c = *(const float4*)&ew1[(size_t)512 * DFF + lane * 4];
    float4 b14 = *(const float4*)&b1[lane * 4];
    float4 w24 = *(const float4*)&w2[lane * 4];
    float b2s = b2v[0];
    float4 h1 = *(const float4*)&g_h12[(size_t)p * 256 + lane * 4];
    float bx = h1.x + b14.x, by = h1.y + b14.y;
    float bz = h1.z + b14.z, bw = h1.w + b14.w;
    size_t ebase = (size_t)p * KNN;
    #pragma unroll
    for (int i = 0; i < KNN; ++i) {
        int dst = g_dst[ebase + i];
        float val = g_val[ebase + i];
        float4 h2 = *(const float4*)&g_h12[((size_t)(b*N_ + dst)) * 256 + 128 + lane * 4];
        float x0 = bx + h2.x + val * w1c.x;
        float x1 = by + h2.y + val * w1c.y;
        float x2 = bz + h2.z + val * w1c.z;
        float x3 = bw + h2.w + val * w1c.w;
        x0 = x0 > 0.f ? x0 : expm1f(x0);
        x1 = x1 > 0.f ? x1 : expm1f(x1);
        x2 = x2 > 0.f ? x2 : expm1f(x2);
        x3 = x3 > 0.f ? x3 : expm1f(x3);
        float s = x0 * w24.x + x1 * w24.y + x2 * w24.z + x3 * w24.w;
        #pragma unroll
        for (int off = 16; off; off >>= 1) s += __shfl_down_sync(0xffffffffu, s, off);
        if (lane == 0) {
            int eid = (int)ebase + i;
            if (3*E_TOT + eid < out_size)
                out[3*E_TOT + eid] = 1.f / (1.f + expf(-(s + b2s)));
            if (eid*3 + 2 < out_size) {
                out[eid*3 + 0] = (float)b;
                out[eid*3 + 1] = (float)src;
                out[eid*3 + 2] = (float)dst;
            }
        }
    }
}

// -----------------------------------------------------------------------------
extern "C" void kernel_launch(void* const* d_in, const int* in_sizes, int n_in,
                              void* d_out, int out_size) {
    const float* inputs  = (const float*)d_in[0];
    const float* enc_w1  = (const float*)d_in[1];
    const float* enc_b1  = (const float*)d_in[2];
    const float* enc_w2  = (const float*)d_in[3];
    const float* enc_b2  = (const float*)d_in[4];
    const float* edge_w1 = (const float*)d_in[5];
    const float* edge_b1 = (const float*)d_in[6];
    const float* edge_w2 = (const float*)d_in[7];
    const float* edge_b2 = (const float*)d_in[8];
    const float* rot     = (const float*)d_in[9];
    float* out = (float*)d_out;

    size_t enc_smem = (size_t)(16384 + 16384) * sizeof(float);   // 128 KB
    cudaFuncSetAttribute(enc_kernel, cudaFuncAttributeMaxDynamicSharedMemorySize,
                         (int)enc_smem);
    enc_kernel<<<(B_*N_)/ENC_PTS, 512, enc_smem>>>(inputs, enc_w1, enc_b1,
                                                   enc_w2, enc_b2, rot);

    size_t h12_smem = (size_t)(8192 + 16384) * sizeof(float);    // 96 KB
    cudaFuncSetAttribute(h12_kernel, cudaFuncAttributeMaxDynamicSharedMemorySize,
                         (int)h12_smem);
    h12_kernel<<<(B_*N_)/128, 512, h12_smem>>>(inputs, edge_w1);

    sort_kernel<<<B_, 256>>>(out, out_size);

    size_t tk_smem = (size_t)(2 * TKC * 128 + 2 * TKC) * sizeof(float)
                   + 128 * 8 * sizeof(unsigned long long);       // ~41 KB
    cudaFuncSetAttribute(topk_kernel, cudaFuncAttributeMaxDynamicSharedMemorySize,
                         (int)tk_smem);
    topk_kernel<<<B_*NBINS*4, 256, tk_smem>>>();

    edge_kernel<<<(B_*N_)/8, 256>>>(edge_w1, edge_b1, edge_w2, edge_b2,
                                    out, out_size);
}